// round 13
// baseline (speedup 1.0000x reference)
#include <cuda_runtime.h>
#include <cuda_bf16.h>
#include <math.h>
#include <float.h>
#include <stdint.h>

// Problem constants
constexpr int NB = 2;
constexpr int NS = 1024;
constexpr int NC = 1024;
constexpr int NH = 16;
constexpr int HD = 64;
constexpr int NE = 4;

// ---------------------------------------------------------------------------
// Scratch (device globals)
// ---------------------------------------------------------------------------
__device__ float g_comb[NB*NS*NC];
__device__ float g_x   [NB*NS*NC];

__device__ __nv_bfloat16 g_cxh[NB*NS*NC],    g_cxl[NB*NS*NC];
__device__ __nv_bfloat16 g_aeh[NB*2*NS*NC],  g_ael[NB*2*NS*NC];
__device__ __nv_bfloat16 g_qh [NB*NS*NC],    g_ql [NB*NS*NC];
__device__ __nv_bfloat16 g_kh [NB*2*NS*NC],  g_kl [NB*2*NS*NC];
__device__ __nv_bfloat16 g_vh [NB*2*NS*NC],  g_vl [NB*2*NS*NC];
__device__ __nv_bfloat16 g_oh [NB*NS*NC],    g_ol [NB*NS*NC];
__device__ __nv_bfloat16 g_hh [NB*NS*NC],    g_hl [NB*NS*NC];
__device__ __nv_bfloat16 g_m1h[NB*NS*NE*NC], g_m1l[NB*NS*NE*NC];

__device__ __nv_bfloat16 g_wthi[12u<<20];
__device__ __nv_bfloat16 g_wtlo[12u<<20];
constexpr size_t WT_Q = 0;
constexpr size_t WT_K = (size_t)1<<20;
constexpr size_t WT_V = (size_t)2<<20;
constexpr size_t WT_O = (size_t)3<<20;
constexpr size_t WT_1 = (size_t)4<<20;
constexpr size_t WT_2 = (size_t)8<<20;

// ---------------------------------------------------------------------------
// Helpers
// ---------------------------------------------------------------------------
__device__ __forceinline__ uint32_t smem_u32(const void* p) {
    uint32_t a;
    asm("{ .reg .u64 t; cvta.to.shared.u64 t, %1; cvt.u32.u64 %0, t; }" : "=r"(a) : "l"(p));
    return a;
}
__device__ __forceinline__ uint32_t pack_bf(float a, float b) {
    __nv_bfloat162 h = __floats2bfloat162_rn(a, b);
    return *reinterpret_cast<uint32_t*>(&h);
}
__device__ __forceinline__ void split2(float a, float b, uint32_t& hi, uint32_t& lo) {
    __nv_bfloat16 ha = __float2bfloat16_rn(a);
    __nv_bfloat16 hb = __float2bfloat16_rn(b);
    hi = pack_bf(a, b);
    lo = pack_bf(a - __bfloat162float(ha), b - __bfloat162float(hb));
}
__device__ __forceinline__ void ldm_x4(uint32_t* r, uint32_t addr) {
    asm volatile("ldmatrix.sync.aligned.m8n8.x4.shared.b16 {%0,%1,%2,%3}, [%4];"
        : "=r"(r[0]), "=r"(r[1]), "=r"(r[2]), "=r"(r[3]) : "r"(addr));
}
__device__ __forceinline__ void ldm_x4_t(uint32_t* r, uint32_t addr) {
    asm volatile("ldmatrix.sync.aligned.m8n8.x4.trans.shared.b16 {%0,%1,%2,%3}, [%4];"
        : "=r"(r[0]), "=r"(r[1]), "=r"(r[2]), "=r"(r[3]) : "r"(addr));
}
__device__ __forceinline__ void mma16816(float* d, const uint32_t* a, uint32_t b0, uint32_t b1) {
    asm volatile(
        "mma.sync.aligned.m16n8k16.row.col.f32.bf16.bf16.f32 "
        "{%0,%1,%2,%3}, {%4,%5,%6,%7}, {%8,%9}, {%0,%1,%2,%3};"
        : "+f"(d[0]), "+f"(d[1]), "+f"(d[2]), "+f"(d[3])
        : "r"(a[0]), "r"(a[1]), "r"(a[2]), "r"(a[3]), "r"(b0), "r"(b1));
}
#define CP16(dst, src) \
    asm volatile("cp.async.cg.shared.global [%0], [%1], 16;" :: "r"(dst), "l"(src))
#define CP_COMMIT() asm volatile("cp.async.commit_group;")
#define CP_WAIT0()  asm volatile("cp.async.wait_group 0;")
#define CP_WAIT1()  asm volatile("cp.async.wait_group 1;")

// ---------------------------------------------------------------------------
// Merged weight transform
// ---------------------------------------------------------------------------
__global__ void wt_split_all(const float* __restrict__ Wq, const float* __restrict__ Wk,
                             const float* __restrict__ Wv, const float* __restrict__ Wo,
                             const float* __restrict__ W1, const float* __restrict__ W2,
                             __nv_bfloat16* __restrict__ hi_base,
                             __nv_bfloat16* __restrict__ lo_base)
{
    int z = blockIdx.x;
    const float* W; size_t off; int K, N, bx, by;
    if (z < 1024)      { W = Wq; off = WT_Q; K = 1024; N = 1024; bx = z & 31;  by = z >> 5; }
    else if (z < 2048) { int i = z - 1024; W = Wk; off = WT_K; K = 1024; N = 1024; bx = i & 31; by = i >> 5; }
    else if (z < 3072) { int i = z - 2048; W = Wv; off = WT_V; K = 1024; N = 1024; bx = i & 31; by = i >> 5; }
    else if (z < 4096) { int i = z - 3072; W = Wo; off = WT_O; K = 1024; N = 1024; bx = i & 31; by = i >> 5; }
    else if (z < 8192) { int i = z - 4096; W = W1; off = WT_1; K = 1024; N = 4096; bx = i & 127; by = i >> 7; }
    else               { int i = z - 8192; W = W2; off = WT_2; K = 4096; N = 1024; bx = i & 31;  by = i >> 5; }
    __nv_bfloat16* hi = hi_base + off;
    __nv_bfloat16* lo = lo_base + off;

    __shared__ float t[32][33];
    int n0 = bx * 32, k0 = by * 32;
    #pragma unroll
    for (int i = 0; i < 4; i++) {
        int k = k0 + threadIdx.y + 8*i;
        t[threadIdx.y + 8*i][threadIdx.x] = W[(size_t)k*N + n0 + threadIdx.x];
    }
    __syncthreads();
    #pragma unroll
    for (int i = 0; i < 4; i++) {
        int n = n0 + threadIdx.y + 8*i;
        int k = k0 + threadIdx.x;
        float v = t[threadIdx.x][threadIdx.y + 8*i];
        __nv_bfloat16 h = __float2bfloat16_rn(v);
        __nv_bfloat16 l = __float2bfloat16_rn(v - __bfloat162float(h));
        hi[(size_t)n*K + k] = h;
        lo[(size_t)n*K + k] = l;
    }
}

// ---------------------------------------------------------------------------
// GEMM core v3: BM=64, BK=32, 3-stage cp.async, ONE barrier per chunk.
// 256 threads = 8 warps (2M x 4N), warp tile 32x32.
// ---------------------------------------------------------------------------
constexpr int BLDS = 40;
constexpr int G_ASZ = 64*BLDS;                 // 2560 elems per A term
constexpr int G_BSZ = 128*BLDS;                // 5120 elems per B term
constexpr int G_SSZ = 2*G_ASZ + 2*G_BSZ;       // 15360 elems per stage
constexpr int GEMM_SMEM = 3 * G_SSZ * 2;       // 92160 bytes

__device__ __forceinline__ void gemm_stage(
    const __nv_bfloat16* Ahi, const __nv_bfloat16* Alo, int lda,
    const __nv_bfloat16* Bhi, const __nv_bfloat16* Blo, int K,
    int tileM, int tileN, int k0, uint32_t sbase, int tid)
{
    const int sr = tid >> 2, sc = (tid & 3) * 8;
    {   // A: 64 x 32, hi+lo
        uint32_t so = (sr*BLDS + sc) * 2;
        size_t ga = (size_t)(tileM + sr)*lda + k0 + sc;
        CP16(sbase + so,             Ahi + ga);
        CP16(sbase + G_ASZ*2 + so,   Alo + ga);
    }
    #pragma unroll
    for (int p = 0; p < 2; p++) {   // B: 128 x 32, hi+lo
        int r = sr + p*64;
        uint32_t so = (r*BLDS + sc) * 2;
        size_t ga = (size_t)(tileN + r)*K + k0 + sc;
        CP16(sbase + 2*G_ASZ*2 + so,           Bhi + ga);
        CP16(sbase + (2*G_ASZ+G_BSZ)*2 + so,   Blo + ga);
    }
    CP_COMMIT();
}

__device__ __forceinline__ void gemm_core64(
    const __nv_bfloat16* __restrict__ Ahi, const __nv_bfloat16* __restrict__ Alo, int lda,
    const __nv_bfloat16* __restrict__ Bhi, const __nv_bfloat16* __restrict__ Blo, int K,
    int tileM, int tileN, uint32_t smb, float (&acc)[2][4][4])
{
    const int tid = threadIdx.x, lane = tid & 31, wid = tid >> 5;
    const int wm = wid >> 2, wn = wid & 3;          // 2 x 4 warps
    const int a_row = wm*32 + (lane & 15);
    const int b_row = wn*32 + (lane & 15);
    const int half8 = (lane >> 4) << 3;
    const int nch = K >> 5;                          // >= 2 always here

    // prologue: stage chunks 0 and 1
    gemm_stage(Ahi, Alo, lda, Bhi, Blo, K, tileM, tileN, 0,  smb,                       tid);
    gemm_stage(Ahi, Alo, lda, Bhi, Blo, K, tileM, tileN, 32, smb + (uint32_t)G_SSZ*2,   tid);

    for (int c = 0; c < nch; c++) {
        if (c + 1 < nch) { CP_WAIT1(); } else { CP_WAIT0(); }
        __syncthreads();
        if (c + 2 < nch) {
            int st2 = (c + 2) % 3;
            gemm_stage(Ahi, Alo, lda, Bhi, Blo, K, tileM, tileN, (c + 2) << 5,
                       smb + (uint32_t)(st2 * G_SSZ) * 2, tid);
        }

        const uint32_t sbase = smb + (uint32_t)((c % 3) * G_SSZ) * 2;
        #pragma unroll
        for (int ks = 0; ks < 32; ks += 16) {
            uint32_t ahi[2][4], alo[2][4];
            #pragma unroll
            for (int mt = 0; mt < 2; mt++) {
                uint32_t off = ((a_row + mt*16)*BLDS + ks + half8) * 2;
                ldm_x4(ahi[mt], sbase + off);
                ldm_x4(alo[mt], sbase + G_ASZ*2 + off);
            }
            uint32_t bh[2][4], bl[2][4];
            #pragma unroll
            for (int p = 0; p < 2; p++) {
                uint32_t off = ((b_row + p*16)*BLDS + ks + half8) * 2;
                ldm_x4(bh[p], sbase + 2*G_ASZ*2 + off);
                ldm_x4(bl[p], sbase + (2*G_ASZ+G_BSZ)*2 + off);
            }
            // term-major batches over 8 distinct accumulators
            #pragma unroll
            for (int p = 0; p < 2; p++)
                #pragma unroll
                for (int mt = 0; mt < 2; mt++) {
                    mma16816(acc[mt][p*2],   ahi[mt], bh[p][0], bh[p][2]);
                    mma16816(acc[mt][p*2+1], ahi[mt], bh[p][1], bh[p][3]);
                }
            #pragma unroll
            for (int p = 0; p < 2; p++)
                #pragma unroll
                for (int mt = 0; mt < 2; mt++) {
                    mma16816(acc[mt][p*2],   ahi[mt], bl[p][0], bl[p][2]);
                    mma16816(acc[mt][p*2+1], ahi[mt], bl[p][1], bl[p][3]);
                }
            #pragma unroll
            for (int p = 0; p < 2; p++)
                #pragma unroll
                for (int mt = 0; mt < 2; mt++) {
                    mma16816(acc[mt][p*2],   alo[mt], bh[p][0], bh[p][2]);
                    mma16816(acc[mt][p*2+1], alo[mt], bh[p][1], bh[p][3]);
                }
        }
        // NOTE: no end-of-chunk barrier (3-stage, issue-after-barrier discipline)
    }
}

// ---------------------------------------------------------------------------
// Generic GEMM kernel (Wo / W1 / W2 paths), BM=64
// ---------------------------------------------------------------------------
enum { EPI_ADD = 3, EPI_GELU = 4 };

template<int EPI, bool SPLITOUT>
__global__ __launch_bounds__(256, 2)
void mma_gemm(const __nv_bfloat16* __restrict__ Ahi, const __nv_bfloat16* __restrict__ Alo,
              int lda,
              const __nv_bfloat16* __restrict__ Bhi, const __nv_bfloat16* __restrict__ Blo,
              float* __restrict__ C,
              __nv_bfloat16* __restrict__ Chi, __nv_bfloat16* __restrict__ Clo,
              int ldc, int K,
              const float* __restrict__ bias,
              const float* __restrict__ addm)
{
    extern __shared__ __nv_bfloat16 sm[];
    const uint32_t smb = smem_u32(sm);
    const int lane = threadIdx.x & 31, wid = threadIdx.x >> 5;
    const int wm = wid >> 2, wn = wid & 3;
    const int tileM = blockIdx.y * 64;
    const int tileN = blockIdx.x * 128;

    float acc[2][4][4];
    #pragma unroll
    for (int i = 0; i < 2; i++)
        #pragma unroll
        for (int j = 0; j < 4; j++)
            #pragma unroll
            for (int q = 0; q < 4; q++) acc[i][j][q] = 0.f;

    gemm_core64(Ahi, Alo, lda, Bhi, Blo, K, tileM, tileN, smb, acc);

    #pragma unroll
    for (int mt = 0; mt < 2; mt++) {
        #pragma unroll
        for (int nt = 0; nt < 4; nt++) {
            int gm = tileM + wm*32 + mt*16 + (lane >> 2);
            int gn = tileN + wn*32 + nt*8 + (lane & 3)*2;
            #pragma unroll
            for (int half = 0; half < 2; half++) {
                int gmr = gm + half*8;
                float v0 = acc[mt][nt][half*2], v1 = acc[mt][nt][half*2+1];
                if (EPI == EPI_ADD) {
                    float2 am = *reinterpret_cast<const float2*>(addm + (size_t)gmr*ldc + gn);
                    v0 += bias[gn] + am.x; v1 += bias[gn+1] + am.y;
                } else if (EPI == EPI_GELU) {
                    float t0 = v0 + bias[gn], t1 = v1 + bias[gn+1];
                    v0 = 0.5f*t0*(1.f + erff(t0*0.70710678118654752f));
                    v1 = 0.5f*t1*(1.f + erff(t1*0.70710678118654752f));
                }
                if (SPLITOUT) {
                    uint32_t hi, lo;
                    split2(v0, v1, hi, lo);
                    *reinterpret_cast<uint32_t*>(Chi + (size_t)gmr*ldc + gn) = hi;
                    *reinterpret_cast<uint32_t*>(Clo + (size_t)gmr*ldc + gn) = lo;
                } else {
                    *reinterpret_cast<float2*>(C + (size_t)gmr*ldc + gn) = make_float2(v0, v1);
                }
            }
        }
    }
}

// ---------------------------------------------------------------------------
// Fused QKV GEMM: 1280 CTAs (0..255 Q; 256..1279 KV), BM=64
// ---------------------------------------------------------------------------
__global__ __launch_bounds__(256, 2)
void mma_qkv(const __nv_bfloat16* __restrict__ cxh, const __nv_bfloat16* __restrict__ cxl,
             const __nv_bfloat16* __restrict__ aeh, const __nv_bfloat16* __restrict__ ael,
             const __nv_bfloat16* __restrict__ wthi, const __nv_bfloat16* __restrict__ wtlo,
             __nv_bfloat16* __restrict__ qh, __nv_bfloat16* __restrict__ ql,
             __nv_bfloat16* __restrict__ kh, __nv_bfloat16* __restrict__ kl,
             __nv_bfloat16* __restrict__ vh, __nv_bfloat16* __restrict__ vl,
             const float* __restrict__ bq, const float* __restrict__ bk,
             const float* __restrict__ bv, const float* __restrict__ pos)
{
    extern __shared__ __nv_bfloat16 sm[];
    const uint32_t smb = smem_u32(sm);

    const int bz = blockIdx.x;
    const bool isQ = bz < 256;
    const __nv_bfloat16 *Ah, *Al, *Bh, *Bl;
    int tileM, tileN;
    if (isQ) {
        int nx = bz & 7, ny = bz >> 3;           // 8 col x 32 row tiles (2048 rows)
        tileM = ny * 64; tileN = nx * 128;
        Ah = cxh; Al = cxl; Bh = wthi + WT_Q; Bl = wtlo + WT_Q;
    } else {
        int i = bz - 256;                         // 1024 CTAs
        int nx = i & 15, ny = i >> 4;             // 16 col (K|V) x 64 row tiles (4096 rows)
        tileM = ny * 64; tileN = nx * 128;
        Ah = aeh; Al = ael; Bh = wthi + WT_K; Bl = wtlo + WT_K;
    }

    const int lane = threadIdx.x & 31, wid = threadIdx.x >> 5;
    const int wm = wid >> 2, wn = wid & 3;

    float acc[2][4][4];
    #pragma unroll
    for (int i = 0; i < 2; i++)
        #pragma unroll
        for (int j = 0; j < 4; j++)
            #pragma unroll
            for (int q = 0; q < 4; q++) acc[i][j][q] = 0.f;

    gemm_core64(Ah, Al, NC, Bh, Bl, NC, tileM, tileN, smb, acc);

    #pragma unroll
    for (int mt = 0; mt < 2; mt++) {
        #pragma unroll
        for (int nt = 0; nt < 4; nt++) {
            int gm = tileM + wm*32 + mt*16 + (lane >> 2);
            int gn = tileN + wn*32 + nt*8 + (lane & 3)*2;
            #pragma unroll
            for (int half = 0; half < 2; half++) {
                int gmr = gm + half*8;
                float v0 = acc[mt][nt][half*2], v1 = acc[mt][nt][half*2+1];
                const float* pr = pos + (gmr % NS)*HD;
                uint32_t hi, lo;
                if (isQ) {
                    v0 = (v0 + bq[gn]   + pr[gn & (HD-1)])     * 0.125f;
                    v1 = (v1 + bq[gn+1] + pr[(gn+1) & (HD-1)]) * 0.125f;
                    split2(v0, v1, hi, lo);
                    *reinterpret_cast<uint32_t*>(qh + (size_t)gmr*NC + gn) = hi;
                    *reinterpret_cast<uint32_t*>(ql + (size_t)gmr*NC + gn) = lo;
                } else if (gn < NC) {
                    v0 = v0 + bk[gn]   + pr[gn & (HD-1)];
                    v1 = v1 + bk[gn+1] + pr[(gn+1) & (HD-1)];
                    split2(v0, v1, hi, lo);
                    *reinterpret_cast<uint32_t*>(kh + (size_t)gmr*NC + gn) = hi;
                    *reinterpret_cast<uint32_t*>(kl + (size_t)gmr*NC + gn) = lo;
                } else {
                    int gv = gn - NC;
                    v0 += bv[gv]; v1 += bv[gv+1];
                    split2(v0, v1, hi, lo);
                    *reinterpret_cast<uint32_t*>(vh + (size_t)gmr*NC + gv) = hi;
                    *reinterpret_cast<uint32_t*>(vl + (size_t)gmr*NC + gv) = lo;
                }
            }
        }
    }
}

// ---------------------------------------------------------------------------
// Flash attention v2 (unchanged from round 12)
// ---------------------------------------------------------------------------
constexpr int FLS  = 72;
constexpr int FQ_HI = 0;
constexpr int FQ_LO = 128*FLS;
constexpr int FKV   = 2*128*FLS;
constexpr int KVB   = 64*FLS;
constexpr int KVST  = 4*KVB;
constexpr int FLASH_SMEM = (2*128*FLS + 2*KVST) * 2;

__global__ __launch_bounds__(256, 2)
void flash_kernel(const __nv_bfloat16* __restrict__ qh, const __nv_bfloat16* __restrict__ ql,
                  const __nv_bfloat16* __restrict__ kh, const __nv_bfloat16* __restrict__ kl,
                  const __nv_bfloat16* __restrict__ vh, const __nv_bfloat16* __restrict__ vl,
                  __nv_bfloat16* __restrict__ oh, __nv_bfloat16* __restrict__ ol)
{
    extern __shared__ __nv_bfloat16 sf[];
    const uint32_t smb = smem_u32(sf);
    const int tid = threadIdx.x, lane = tid & 31, wid = tid >> 5;
    const int bh = blockIdx.y, b = bh >> 4, h = bh & 15;
    const int bx = blockIdx.x;
    const int q0 = bx * 128;
    const size_t qoff = (size_t)b*NS*NC   + h*HD;
    const size_t koff = (size_t)b*2*NS*NC + h*HD;

    {
        const int r = tid >> 1, c0 = (tid & 1) * 32;
        #pragma unroll
        for (int i = 0; i < 4; i++) {
            int cc = c0 + i*8;
            size_t ga = qoff + (size_t)(q0 + r)*NC + cc;
            uint32_t so = (r*FLS + cc) * 2;
            CP16(smb + FQ_HI*2 + so, qh + ga);
            CP16(smb + FQ_LO*2 + so, ql + ga);
        }
        CP_COMMIT(); CP_WAIT0();
    }
    __syncthreads();

    const int arow = wid*16 + (lane & 15);
    const int half8 = (lane >> 4) << 3;
    uint32_t qhi4[4][4], qlo4[4][4];
    #pragma unroll
    for (int kc = 0; kc < 4; kc++) {
        uint32_t off = (arow*FLS + kc*16 + half8) * 2;
        ldm_x4(qhi4[kc], smb + FQ_HI*2 + off);
        ldm_x4(qlo4[kc], smb + FQ_LO*2 + off);
    }

    float om[8][4];
    #pragma unroll
    for (int i = 0; i < 8; i++)
        #pragma unroll
        for (int j = 0; j < 4; j++) om[i][j] = 0.f;
    float m_i0 = -1e30f, m_i1 = -1e30f, l_i0 = 0.f, l_i1 = 0.f;

    const int qrow0 = q0 + wid*16 + (lane >> 2);

    const int fe = 2*bx + 1;
    const int bs = 16 + 2*bx;
    constexpr int NT_ACT = 18;

    const int sr = tid >> 2, sc0 = (tid & 3) * 16;

    {
        uint32_t base = smb + (uint32_t)(FKV + 0*KVST)*2;
        #pragma unroll
        for (int i = 0; i < 2; i++) {
            int cc = sc0 + i*8;
            size_t ga = koff + (size_t)(0 + sr)*NC + cc;
            uint32_t so = (sr*FLS + cc) * 2;
            CP16(base + so,           kh + ga);
            CP16(base + KVB*2 + so,   kl + ga);
            CP16(base + 2*KVB*2 + so, vh + ga);
            CP16(base + 3*KVB*2 + so, vl + ga);
        }
        CP_COMMIT();
    }

    for (int it = 0; it < NT_ACT; it++) {
        const int kt = (it <= fe) ? it : (bs + (it - fe - 1));
        const int st = it & 1;

        if (it + 1 < NT_ACT) {
            const int ktn = (it + 1 <= fe) ? (it + 1) : (bs + (it + 1 - fe - 1));
            const int kg0n = ktn * 64;
            uint32_t base = smb + (uint32_t)(FKV + (st ^ 1)*KVST)*2;
            #pragma unroll
            for (int i = 0; i < 2; i++) {
                int cc = sc0 + i*8;
                size_t ga = koff + (size_t)(kg0n + sr)*NC + cc;
                uint32_t so = (sr*FLS + cc) * 2;
                CP16(base + so,           kh + ga);
                CP16(base + KVB*2 + so,   kl + ga);
                CP16(base + 2*KVB*2 + so, vh + ga);
                CP16(base + 3*KVB*2 + so, vl + ga);
            }
            CP_COMMIT();
            CP_WAIT1();
        } else {
            CP_WAIT0();
        }
        __syncthreads();

        const uint32_t kvb = smb + (uint32_t)(FKV + st*KVST)*2;
        const int kg0 = kt * 64;
        const bool fwdh = kt < 16;
        const bool full = fwdh ? (kt <= 2*bx - 1) : (kt >= 18 + 2*bx);

        float s[8][4];
        #pragma unroll
        for (int i = 0; i < 8; i++)
            #pragma unroll
            for (int j = 0; j < 4; j++) s[i][j] = 0.f;
        #pragma unroll
        for (int kc = 0; kc < 4; kc++) {
            #pragma unroll
            for (int np0 = 0; np0 < 4; np0 += 2) {
                uint32_t bh4[2][4], bl4[2][4];
                #pragma unroll
                for (int p = 0; p < 2; p++) {
                    uint32_t off = (((np0+p)*16 + (lane & 15))*FLS + kc*16 + half8) * 2;
                    ldm_x4(bh4[p], kvb + off);
                    ldm_x4(bl4[p], kvb + KVB*2 + off);
                }
                #pragma unroll
                for (int p = 0; p < 2; p++) {
                    mma16816(s[(np0+p)*2],   qhi4[kc], bh4[p][0], bh4[p][2]);
                    mma16816(s[(np0+p)*2+1], qhi4[kc], bh4[p][1], bh4[p][3]);
                }
                #pragma unroll
                for (int p = 0; p < 2; p++) {
                    mma16816(s[(np0+p)*2],   qhi4[kc], bl4[p][0], bl4[p][2]);
                    mma16816(s[(np0+p)*2+1], qhi4[kc], bl4[p][1], bl4[p][3]);
                }
                #pragma unroll
                for (int p = 0; p < 2; p++) {
                    mma16816(s[(np0+p)*2],   qlo4[kc], bh4[p][0], bh4[p][2]);
                    mma16816(s[(np0+p)*2+1], qlo4[kc], bh4[p][1], bh4[p][3]);
                }
            }
        }

        if (!full) {
            #pragma unroll
            for (int nt = 0; nt < 8; nt++) {
                int kbase = kg0 + nt*8 + (lane & 3)*2;
                #pragma unroll
                for (int d = 0; d < 2; d++) {
                    int kidx = kbase + d;
                    bool ok0, ok1;
                    if (fwdh) { ok0 = (kidx <= qrow0); ok1 = (kidx <= qrow0 + 8); }
                    else      { int j = kidx - 1024; ok0 = (j >= qrow0); ok1 = (j >= qrow0 + 8); }
                    if (!ok0) s[nt][d]     = -1e30f;
                    if (!ok1) s[nt][d + 2] = -1e30f;
                }
            }
        }

        float mx0 = -1e30f, mx1 = -1e30f;
        #pragma unroll
        for (int nt = 0; nt < 8; nt++) {
            mx0 = fmaxf(mx0, fmaxf(s[nt][0], s[nt][1]));
            mx1 = fmaxf(mx1, fmaxf(s[nt][2], s[nt][3]));
        }
        mx0 = fmaxf(mx0, __shfl_xor_sync(0xffffffffu, mx0, 1));
        mx0 = fmaxf(mx0, __shfl_xor_sync(0xffffffffu, mx0, 2));
        mx1 = fmaxf(mx1, __shfl_xor_sync(0xffffffffu, mx1, 1));
        mx1 = fmaxf(mx1, __shfl_xor_sync(0xffffffffu, mx1, 2));
        float mn0 = fmaxf(m_i0, mx0), mn1 = fmaxf(m_i1, mx1);
        float sc0f = __expf(m_i0 - mn0), sc1f = __expf(m_i1 - mn1);
        m_i0 = mn0; m_i1 = mn1;
        float rs0 = 0.f, rs1 = 0.f;
        #pragma unroll
        for (int nt = 0; nt < 8; nt++) {
            s[nt][0] = __expf(s[nt][0] - mn0);
            s[nt][1] = __expf(s[nt][1] - mn0);
            s[nt][2] = __expf(s[nt][2] - mn1);
            s[nt][3] = __expf(s[nt][3] - mn1);
            rs0 += s[nt][0] + s[nt][1];
            rs1 += s[nt][2] + s[nt][3];
        }
        rs0 += __shfl_xor_sync(0xffffffffu, rs0, 1);
        rs0 += __shfl_xor_sync(0xffffffffu, rs0, 2);
        rs1 += __shfl_xor_sync(0xffffffffu, rs1, 1);
        rs1 += __shfl_xor_sync(0xffffffffu, rs1, 2);
        l_i0 = l_i0 * sc0f + rs0;
        l_i1 = l_i1 * sc1f + rs1;
        #pragma unroll
        for (int nt = 0; nt < 8; nt++) {
            om[nt][0] *= sc0f; om[nt][1] *= sc0f;
            om[nt][2] *= sc1f; om[nt][3] *= sc1f;
        }

        #pragma unroll
        for (int kc = 0; kc < 4; kc++) {
            uint32_t ph[4], pl[4];
            split2(s[2*kc][0],   s[2*kc][1],   ph[0], pl[0]);
            split2(s[2*kc][2],   s[2*kc][3],   ph[1], pl[1]);
            split2(s[2*kc+1][0], s[2*kc+1][1], ph[2], pl[2]);
            split2(s[2*kc+1][2], s[2*kc+1][3], ph[3], pl[3]);
            const int vm = lane >> 3, vr = lane & 7;
            #pragma unroll
            for (int hp0 = 0; hp0 < 4; hp0 += 2) {
                uint32_t vh4[2][4], vl4[2][4];
                #pragma unroll
                for (int p = 0; p < 2; p++) {
                    uint32_t vaddr = ((kc*16 + (vm & 1)*8 + vr)*FLS + (hp0+p)*16 + (vm >> 1)*8) * 2;
                    ldm_x4_t(vh4[p], kvb + 2*KVB*2 + vaddr);
                    ldm_x4_t(vl4[p], kvb + 3*KVB*2 + vaddr);
                }
                #pragma unroll
                for (int p = 0; p < 2; p++) {
                    mma16816(om[(hp0+p)*2],   ph, vh4[p][0], vh4[p][1]);
                    mma16816(om[(hp0+p)*2+1], ph, vh4[p][2], vh4[p][3]);
                }
                #pragma unroll
                for (int p = 0; p < 2; p++) {
                    mma16816(om[(hp0+p)*2],   pl, vh4[p][0], vh4[p][1]);
                    mma16816(om[(hp0+p)*2+1], pl, vh4[p][2], vh4[p][3]);
                }
                #pragma unroll
                for (int p = 0; p < 2; p++) {
                    mma16816(om[(hp0+p)*2],   ph, vl4[p][0], vl4[p][1]);
                    mma16816(om[(hp0+p)*2+1], ph, vl4[p][2], vl4[p][3]);
                }
            }
        }
        __syncthreads();
    }

    float il0 = 1.f / l_i0, il1 = 1.f / l_i1;
    #pragma unroll
    for (int nt = 0; nt < 8; nt++) {
        int hd = nt*8 + (lane & 3)*2;
        uint32_t hi, lo;
        split2(om[nt][0]*il0, om[nt][1]*il0, hi, lo);
        *reinterpret_cast<uint32_t*>(oh + qoff + (size_t)qrow0*NC + hd) = hi;
        *reinterpret_cast<uint32_t*>(ol + qoff + (size_t)qrow0*NC + hd) = lo;
        split2(om[nt][2]*il1, om[nt][3]*il1, hi, lo);
        *reinterpret_cast<uint32_t*>(oh + qoff + (size_t)(qrow0+8)*NC + hd) = hi;
        *reinterpret_cast<uint32_t*>(ol + qoff + (size_t)(qrow0+8)*NC + hd) = lo;
    }
}

// ---------------------------------------------------------------------------
// Block reduction + LN kernels
// ---------------------------------------------------------------------------
__device__ __forceinline__ float2 block_reduce_sum2(float a, float b) {
    __shared__ float sha[8], shb[8];
    #pragma unroll
    for (int o = 16; o > 0; o >>= 1) {
        a += __shfl_xor_sync(0xffffffffu, a, o);
        b += __shfl_xor_sync(0xffffffffu, b, o);
    }
    int lane = threadIdx.x & 31, w = threadIdx.x >> 5;
    __syncthreads();
    if (lane == 0) { sha[w] = a; shb[w] = b; }
    __syncthreads();
    a = sha[lane & 7]; b = shb[lane & 7];
    #pragma unroll
    for (int o = 4; o > 0; o >>= 1) {
        a += __shfl_xor_sync(0xffffffffu, a, o);
        b += __shfl_xor_sync(0xffffffffu, b, o);
    }
    return make_float2(a, b);
}

__device__ __forceinline__ void store_split(__nv_bfloat16* hi, __nv_bfloat16* lo,
                                            size_t idx, float y) {
    __nv_bfloat16 hv = __float2bfloat16_rn(y);
    hi[idx] = hv;
    lo[idx] = __float2bfloat16_rn(y - __bfloat162float(hv));
}

__global__ void ln_all(const float* __restrict__ fwd, const float* __restrict__ bwd,
                       const float* __restrict__ g, const float* __restrict__ bta,
                       float* __restrict__ comb,
                       __nv_bfloat16* __restrict__ cxh, __nv_bfloat16* __restrict__ cxl,
                       __nv_bfloat16* __restrict__ aeh, __nv_bfloat16* __restrict__ ael)
{
    int z = blockIdx.x;
    if (z < NB*NS) {
        int row = z;
        int b = row / NS, s = row % NS;
        const float* fp = fwd + ((size_t)b*(NS+1) + s) * NC;
        const float* rp = bwd + ((size_t)b*(NS+1) + s + 1) * NC;
        const float rs2 = 0.70710678118654752f;
        float vals[4];
        float sum = 0.f, sq = 0.f;
        #pragma unroll
        for (int t = 0; t < 4; t++) {
            int i = threadIdx.x + t*256;
            float c = (fp[i] + rp[i]) * rs2;
            vals[t] = c; sum += c; sq += c*c;
            comb[(size_t)row*NC + i] = c;
        }
        float2 r2 = block_reduce_sum2(sum, sq);
        float mean = r2.x * (1.f/NC);
        float var  = r2.y * (1.f/NC) - mean*mean;
        float rinv = rsqrtf(var + 1e-5f);
        #pragma unroll
        for (int t = 0; t < 4; t++) {
            int i = threadIdx.x + t*256;
            store_split(cxh, cxl, (size_t)row*NC + i, (vals[t] - mean) * rinv * g[i] + bta[i]);
        }
    } else {
        int row = z - NB*NS;
        int b = row / (2*NS), t = row % (2*NS);
        const float* src = (t < NS) ? fwd + ((size_t)b*(NS+1) + t) * NC
                                    : bwd + ((size_t)b*(NS+1) + (t - NS) + 1) * NC;
        float vals[4];
        float sum = 0.f, sq = 0.f;
        #pragma unroll
        for (int u = 0; u < 4; u++) {
            int i = threadIdx.x + u*256;
            float c = src[i];
            vals[u] = c; sum += c; sq += c*c;
        }
        float2 r2 = block_reduce_sum2(sum, sq);
        float mean = r2.x * (1.f/NC);
        float var  = r2.y * (1.f/NC) - mean*mean;
        float rinv = rsqrtf(var + 1e-5f);
        #pragma unroll
        for (int u = 0; u < 4; u++) {
            int i = threadIdx.x + u*256;
            store_split(aeh, ael, (size_t)row*NC + i, (vals[u] - mean) * rinv * g[i] + bta[i]);
        }
    }
}

__global__ void double_ln_kernel(const float* __restrict__ xin,
                                 const float* __restrict__ g2, const float* __restrict__ b2,
                                 const float* __restrict__ gm, const float* __restrict__ bm,
                                 __nv_bfloat16* __restrict__ hh, __nv_bfloat16* __restrict__ hl)
{
    int row = blockIdx.x;
    const float* xp = xin + (size_t)row*NC;
    float vals[4];
    float s = 0.f, sq = 0.f;
    #pragma unroll
    for (int t = 0; t < 4; t++) {
        int i = threadIdx.x + t*256;
        float vv = xp[i];
        vals[t] = vv; s += vv; sq += vv*vv;
    }
    float2 r2 = block_reduce_sum2(s, sq);
    float mean = r2.x * (1.f/NC);
    float var  = r2.y * (1.f/NC) - mean*mean;
    float rinv = rsqrtf(var + 1e-5f);
    s = 0.f; sq = 0.f;
    #pragma unroll
    for (int t = 0; t < 4; t++) {
        int i = threadIdx.x + t*256;
        float y = (vals[t] - mean) * rinv * g2[i] + b2[i];
        vals[t] = y; s += y; sq += y*y;
    }
    r2 = block_reduce_sum2(s, sq);
    mean = r2.x * (1.f/NC);
    var  = r2.y * (1.f/NC) - mean*mean;
    rinv = rsqrtf(var + 1e-5f);
    #pragma unroll
    for (int t = 0; t < 4; t++) {
        int i = threadIdx.x + t*256;
        store_split(hh, hl, (size_t)row*NC + i, (vals[t] - mean) * rinv * gm[i] + bm[i]);
    }
}

// ---------------------------------------------------------------------------
// Launch
// ---------------------------------------------------------------------------
extern "C" void kernel_launch(void* const* d_in, const int* in_sizes, int n_in,
                              void* d_out, int out_size)
{
    (void)in_sizes; (void)n_in; (void)out_size;
    const float* fwd  = (const float*)d_in[0];
    const float* bwd  = (const float*)d_in[1];
    const float* pos  = (const float*)d_in[2];
    const float* ln1g = (const float*)d_in[3];
    const float* ln1b = (const float*)d_in[4];
    const float* Wq   = (const float*)d_in[5];
    const float* bq   = (const float*)d_in[6];
    const float* Wk   = (const float*)d_in[7];
    const float* bk   = (const float*)d_in[8];
    const float* Wv   = (const float*)d_in[9];
    const float* bv   = (const float*)d_in[10];
    const float* Wo   = (const float*)d_in[11];
    const float* bo   = (const float*)d_in[12];
    const float* ln2g = (const float*)d_in[13];
    const float* ln2b = (const float*)d_in[14];
    const float* mlpg = (const float*)d_in[15];
    const float* mlpb = (const float*)d_in[16];
    const float* W1   = (const float*)d_in[17];
    const float* b1   = (const float*)d_in[18];
    const float* W2   = (const float*)d_in[19];
    const float* b2   = (const float*)d_in[20];
    float* out = (float*)d_out;

    float *comb, *x;
    __nv_bfloat16 *cxh,*cxl,*aeh,*ael,*qh,*ql,*kh,*kl,*vh,*vl,*oh,*ol,*hh,*hl,*m1h,*m1l;
    __nv_bfloat16 *wthi, *wtlo;
    cudaGetSymbolAddress((void**)&comb, g_comb);
    cudaGetSymbolAddress((void**)&x,    g_x);
    cudaGetSymbolAddress((void**)&cxh,  g_cxh);  cudaGetSymbolAddress((void**)&cxl, g_cxl);
    cudaGetSymbolAddress((void**)&aeh,  g_aeh);  cudaGetSymbolAddress((void**)&ael, g_ael);
    cudaGetSymbolAddress((void**)&qh,   g_qh);   cudaGetSymbolAddress((void**)&ql,  g_ql);
    cudaGetSymbolAddress((void**)&kh,   g_kh);   cudaGetSymbolAddress((void**)&kl,  g_kl);
    cudaGetSymbolAddress((void**)&vh,   g_vh);   cudaGetSymbolAddress((void**)&vl,  g_vl);
    cudaGetSymbolAddress((void**)&oh,   g_oh);   cudaGetSymbolAddress((void**)&ol,  g_ol);
    cudaGetSymbolAddress((void**)&hh,   g_hh);   cudaGetSymbolAddress((void**)&hl,  g_hl);
    cudaGetSymbolAddress((void**)&m1h,  g_m1h);  cudaGetSymbolAddress((void**)&m1l, g_m1l);
    cudaGetSymbolAddress((void**)&wthi, g_wthi);
    cudaGetSymbolAddress((void**)&wtlo, g_wtlo);

    cudaFuncSetAttribute(mma_qkv,                   cudaFuncAttributeMaxDynamicSharedMemorySize, GEMM_SMEM);
    cudaFuncSetAttribute(mma_gemm<EPI_ADD,false>,   cudaFuncAttributeMaxDynamicSharedMemorySize, GEMM_SMEM);
    cudaFuncSetAttribute(mma_gemm<EPI_GELU,true>,   cudaFuncAttributeMaxDynamicSharedMemorySize, GEMM_SMEM);
    cudaFuncSetAttribute(flash_kernel,              cudaFuncAttributeMaxDynamicSharedMemorySize, FLASH_SMEM);

    // 1: all weight transforms, one launch
    wt_split_all<<<12288, dim3(32, 8)>>>(Wq, Wk, Wv, Wo, W1, W2, wthi, wtlo);

    // 2: both LayerNorms, one launch
    ln_all<<<NB*NS + NB*2*NS, 256>>>(fwd, bwd, ln1g, ln1b, comb, cxh, cxl, aeh, ael);

    // 3: fused Q+K+V projections (1280 CTAs, BM=64)
    mma_qkv<<<1280, 256, GEMM_SMEM>>>(cxh, cxl, aeh, ael, wthi, wtlo,
                                      qh, ql, kh, kl, vh, vl, bq, bk, bv, pos);

    // 4: fused flash attention
    flash_kernel<<<dim3(NS/128, NB*NH), 256, FLASH_SMEM>>>(qh, ql, kh, kl, vh, vl, oh, ol);

    // 5: x = comb + (o @ Wo + bo)   [256 CTAs]
    mma_gemm<EPI_ADD,false><<<dim3(NC/128, (NB*NS)/64), 256, GEMM_SMEM>>>(
        oh, ol, NC, wthi + WT_O, wtlo + WT_O, x, nullptr, nullptr, NC, NC, bo, comb);

    // 6: h = LN(LN(x))
    double_ln_kernel<<<NB*NS, 256>>>(x, ln2g, ln2b, mlpg, mlpb, hh, hl);

    // 7: m1 = gelu(h @ W1 + b1)   [1024 CTAs]
    mma_gemm<EPI_GELU,true><<<dim3((NE*NC)/128, (NB*NS)/64), 256, GEMM_SMEM>>>(
        hh, hl, NC, wthi + WT_1, wtlo + WT_1, nullptr, m1h, m1l, NE*NC, NC, b1, nullptr);

    // 8: out = x + (m1 @ W2 + b2)   [256 CTAs]
    mma_gemm<EPI_ADD,false><<<dim3(NC/128, (NB*NS)/64), 256, GEMM_SMEM>>>(
        m1h, m1l, NE*NC, wthi + WT_2, wtlo + WT_2, out, nullptr, nullptr, NC, NE*NC, b2, x);
}

// round 14
// speedup vs baseline: 1.0033x; 1.0033x over previous
#include <cuda_runtime.h>
#include <cuda_bf16.h>
#include <math.h>
#include <float.h>
#include <stdint.h>

// Problem constants
constexpr int NB = 2;
constexpr int NS = 1024;
constexpr int NC = 1024;
constexpr int NH = 16;
constexpr int HD = 64;
constexpr int NE = 4;

// ---------------------------------------------------------------------------
// Scratch (device globals)
// ---------------------------------------------------------------------------
__device__ float g_comb[NB*NS*NC];
__device__ float g_x   [NB*NS*NC];

__device__ __nv_bfloat16 g_cxh[NB*NS*NC],    g_cxl[NB*NS*NC];
__device__ __nv_bfloat16 g_aeh[NB*2*NS*NC],  g_ael[NB*2*NS*NC];
__device__ __nv_bfloat16 g_qh [NB*NS*NC],    g_ql [NB*NS*NC];
__device__ __nv_bfloat16 g_kh [NB*2*NS*NC],  g_kl [NB*2*NS*NC];
__device__ __nv_bfloat16 g_vh [NB*2*NS*NC],  g_vl [NB*2*NS*NC];
__device__ __nv_bfloat16 g_oh [NB*NS*NC],    g_ol [NB*NS*NC];
__device__ __nv_bfloat16 g_hh [NB*NS*NC],    g_hl [NB*NS*NC];
__device__ __nv_bfloat16 g_m1h[NB*NS*NE*NC], g_m1l[NB*NS*NE*NC];

__device__ __nv_bfloat16 g_wthi[12u<<20];
__device__ __nv_bfloat16 g_wtlo[12u<<20];
constexpr size_t WT_Q = 0;
constexpr size_t WT_K = (size_t)1<<20;
constexpr size_t WT_V = (size_t)2<<20;
constexpr size_t WT_O = (size_t)3<<20;
constexpr size_t WT_1 = (size_t)4<<20;
constexpr size_t WT_2 = (size_t)8<<20;

// ---------------------------------------------------------------------------
// Helpers
// ---------------------------------------------------------------------------
__device__ __forceinline__ uint32_t smem_u32(const void* p) {
    uint32_t a;
    asm("{ .reg .u64 t; cvta.to.shared.u64 t, %1; cvt.u32.u64 %0, t; }" : "=r"(a) : "l"(p));
    return a;
}
__device__ __forceinline__ uint32_t pack_bf(float a, float b) {
    __nv_bfloat162 h = __floats2bfloat162_rn(a, b);
    return *reinterpret_cast<uint32_t*>(&h);
}
__device__ __forceinline__ void split2(float a, float b, uint32_t& hi, uint32_t& lo) {
    __nv_bfloat16 ha = __float2bfloat16_rn(a);
    __nv_bfloat16 hb = __float2bfloat16_rn(b);
    hi = pack_bf(a, b);
    lo = pack_bf(a - __bfloat162float(ha), b - __bfloat162float(hb));
}
__device__ __forceinline__ void ldm_x4(uint32_t* r, uint32_t addr) {
    asm volatile("ldmatrix.sync.aligned.m8n8.x4.shared.b16 {%0,%1,%2,%3}, [%4];"
        : "=r"(r[0]), "=r"(r[1]), "=r"(r[2]), "=r"(r[3]) : "r"(addr));
}
__device__ __forceinline__ void ldm_x4_t(uint32_t* r, uint32_t addr) {
    asm volatile("ldmatrix.sync.aligned.m8n8.x4.trans.shared.b16 {%0,%1,%2,%3}, [%4];"
        : "=r"(r[0]), "=r"(r[1]), "=r"(r[2]), "=r"(r[3]) : "r"(addr));
}
__device__ __forceinline__ void mma16816(float* d, const uint32_t* a, uint32_t b0, uint32_t b1) {
    asm volatile(
        "mma.sync.aligned.m16n8k16.row.col.f32.bf16.bf16.f32 "
        "{%0,%1,%2,%3}, {%4,%5,%6,%7}, {%8,%9}, {%0,%1,%2,%3};"
        : "+f"(d[0]), "+f"(d[1]), "+f"(d[2]), "+f"(d[3])
        : "r"(a[0]), "r"(a[1]), "r"(a[2]), "r"(a[3]), "r"(b0), "r"(b1));
}
#define CP16(dst, src) \
    asm volatile("cp.async.cg.shared.global [%0], [%1], 16;" :: "r"(dst), "l"(src))
#define CP_COMMIT() asm volatile("cp.async.commit_group;")
#define CP_WAIT0()  asm volatile("cp.async.wait_group 0;")

// ---------------------------------------------------------------------------
// Merged weight transform
// ---------------------------------------------------------------------------
__global__ void wt_split_all(const float* __restrict__ Wq, const float* __restrict__ Wk,
                             const float* __restrict__ Wv, const float* __restrict__ Wo,
                             const float* __restrict__ W1, const float* __restrict__ W2,
                             __nv_bfloat16* __restrict__ hi_base,
                             __nv_bfloat16* __restrict__ lo_base)
{
    int z = blockIdx.x;
    const float* W; size_t off; int K, N, bx, by;
    if (z < 1024)      { W = Wq; off = WT_Q; K = 1024; N = 1024; bx = z & 31;  by = z >> 5; }
    else if (z < 2048) { int i = z - 1024; W = Wk; off = WT_K; K = 1024; N = 1024; bx = i & 31; by = i >> 5; }
    else if (z < 3072) { int i = z - 2048; W = Wv; off = WT_V; K = 1024; N = 1024; bx = i & 31; by = i >> 5; }
    else if (z < 4096) { int i = z - 3072; W = Wo; off = WT_O; K = 1024; N = 1024; bx = i & 31; by = i >> 5; }
    else if (z < 8192) { int i = z - 4096; W = W1; off = WT_1; K = 1024; N = 4096; bx = i & 127; by = i >> 7; }
    else               { int i = z - 8192; W = W2; off = WT_2; K = 4096; N = 1024; bx = i & 31;  by = i >> 5; }
    __nv_bfloat16* hi = hi_base + off;
    __nv_bfloat16* lo = lo_base + off;

    __shared__ float t[32][33];
    int n0 = bx * 32, k0 = by * 32;
    #pragma unroll
    for (int i = 0; i < 4; i++) {
        int k = k0 + threadIdx.y + 8*i;
        t[threadIdx.y + 8*i][threadIdx.x] = W[(size_t)k*N + n0 + threadIdx.x];
    }
    __syncthreads();
    #pragma unroll
    for (int i = 0; i < 4; i++) {
        int n = n0 + threadIdx.y + 8*i;
        int k = k0 + threadIdx.x;
        float v = t[threadIdx.x][threadIdx.y + 8*i];
        __nv_bfloat16 h = __float2bfloat16_rn(v);
        __nv_bfloat16 l = __float2bfloat16_rn(v - __bfloat162float(h));
        hi[(size_t)n*K + k] = h;
        lo[(size_t)n*K + k] = l;
    }
}

// ---------------------------------------------------------------------------
// GEMM core (round-12 layout, single barrier per chunk). BM in {128, 64}.
// ---------------------------------------------------------------------------
constexpr int BLDS = 40;

template<int BM> __host__ __device__ constexpr int NACC_OF() { return 2 * ((128 / (8 / (BM/32))) / 16); }
template<int BM> __host__ __device__ constexpr int SSZ_OF()  { return 2*BM*BLDS + 2*128*BLDS; }
template<int BM> __host__ __device__ constexpr int SMEM_OF() { return 2 * SSZ_OF<BM>() * 2; }

template<int BM>
__device__ __forceinline__ void gemm_stage(
    const __nv_bfloat16* Ahi, const __nv_bfloat16* Alo, int lda,
    const __nv_bfloat16* Bhi, const __nv_bfloat16* Blo, int K,
    int tileM, int tileN, int k0, uint32_t sbase, int tid)
{
    constexpr int ASZ = BM*BLDS;
    constexpr int BSZ = 128*BLDS;
    const int sr0 = tid >> 2, sc0 = (tid & 3) * 8;
    #pragma unroll
    for (int p = 0; p < BM/64; p++) {
        int r = sr0 + p*64;
        uint32_t so = (r*BLDS + sc0) * 2;
        size_t ga = (size_t)(tileM + r)*lda + k0 + sc0;
        CP16(sbase + so,           Ahi + ga);
        CP16(sbase + ASZ*2 + so,   Alo + ga);
    }
    #pragma unroll
    for (int p = 0; p < 2; p++) {
        int r = sr0 + p*64;
        uint32_t so = (r*BLDS + sc0) * 2;
        size_t ga = (size_t)(tileN + r)*K + k0 + sc0;
        CP16(sbase + 2*ASZ*2 + so,         Bhi + ga);
        CP16(sbase + (2*ASZ+BSZ)*2 + so,   Blo + ga);
    }
    CP_COMMIT();
}

template<int BM, int NACC>
__device__ __forceinline__ void gemm_core(
    const __nv_bfloat16* __restrict__ Ahi, const __nv_bfloat16* __restrict__ Alo, int lda,
    const __nv_bfloat16* __restrict__ Bhi, const __nv_bfloat16* __restrict__ Blo, int K,
    int tileM, int tileN, uint32_t smb, float (&acc)[2][NACC][4])
{
    constexpr int WMW = BM/32;
    constexpr int WNW = 8/WMW;
    constexpr int NSPAN = 128/WNW;
    constexpr int NTP = NSPAN/16;
    static_assert(NACC == 2*NTP, "acc shape");
    static_assert((NTP & 1) == 0, "NTP even");
    constexpr int ASZ = BM*BLDS;
    constexpr int BSZ = 128*BLDS;
    constexpr int SSZ = 2*ASZ + 2*BSZ;

    const int tid = threadIdx.x, lane = tid & 31, wid = tid >> 5;
    const int wm = wid / WNW, wn = wid % WNW;
    const int a_row = wm*32 + (lane & 15);
    const int b_row = wn*NSPAN + (lane & 15);
    const int half8 = (lane >> 4) << 3;
    const int nch = K >> 5;

    // prologue: stage chunk 0 into stage 0
    gemm_stage<BM>(Ahi, Alo, lda, Bhi, Blo, K, tileM, tileN, 0, smb, tid);

    for (int c = 0; c < nch; c++) {
        const int st = c & 1;
        CP_WAIT0();
        __syncthreads();
        // issue-after-barrier: all warps have finished reading stage st^1
        if (c + 1 < nch) {
            gemm_stage<BM>(Ahi, Alo, lda, Bhi, Blo, K, tileM, tileN, (c + 1) << 5,
                           smb + (uint32_t)((st ^ 1) * SSZ) * 2, tid);
        }

        const uint32_t sbase = smb + (uint32_t)(st * SSZ * 2);
        #pragma unroll
        for (int ks = 0; ks < 32; ks += 16) {
            uint32_t ahi[2][4], alo[2][4];
            #pragma unroll
            for (int mt = 0; mt < 2; mt++) {
                uint32_t off = ((a_row + mt*16)*BLDS + ks + half8) * 2;
                ldm_x4(ahi[mt], sbase + off);
                ldm_x4(alo[mt], sbase + ASZ*2 + off);
            }
            #pragma unroll
            for (int np0 = 0; np0 < NTP; np0 += 2) {
                uint32_t bh[2][4], bl[2][4];
                #pragma unroll
                for (int p = 0; p < 2; p++) {
                    uint32_t off = ((b_row + (np0+p)*16)*BLDS + ks + half8) * 2;
                    ldm_x4(bh[p], sbase + 2*ASZ*2 + off);
                    ldm_x4(bl[p], sbase + (2*ASZ+BSZ)*2 + off);
                }
                #pragma unroll
                for (int p = 0; p < 2; p++)
                    #pragma unroll
                    for (int mt = 0; mt < 2; mt++) {
                        mma16816(acc[mt][(np0+p)*2],   ahi[mt], bh[p][0], bh[p][2]);
                        mma16816(acc[mt][(np0+p)*2+1], ahi[mt], bh[p][1], bh[p][3]);
                    }
                #pragma unroll
                for (int p = 0; p < 2; p++)
                    #pragma unroll
                    for (int mt = 0; mt < 2; mt++) {
                        mma16816(acc[mt][(np0+p)*2],   ahi[mt], bl[p][0], bl[p][2]);
                        mma16816(acc[mt][(np0+p)*2+1], ahi[mt], bl[p][1], bl[p][3]);
                    }
                #pragma unroll
                for (int p = 0; p < 2; p++)
                    #pragma unroll
                    for (int mt = 0; mt < 2; mt++) {
                        mma16816(acc[mt][(np0+p)*2],   alo[mt], bh[p][0], bh[p][2]);
                        mma16816(acc[mt][(np0+p)*2+1], alo[mt], bh[p][1], bh[p][3]);
                    }
            }
        }
        // no end-of-chunk barrier (issue-after-barrier discipline)
    }
}

// ---------------------------------------------------------------------------
// Generic GEMM kernel (Wo / W1 / W2 paths)
// ---------------------------------------------------------------------------
enum { EPI_ADD = 3, EPI_GELU = 4 };

template<int BM, int EPI, bool SPLITOUT>
__global__ __launch_bounds__(256, 2)
void mma_gemm(const __nv_bfloat16* __restrict__ Ahi, const __nv_bfloat16* __restrict__ Alo,
              int lda,
              const __nv_bfloat16* __restrict__ Bhi, const __nv_bfloat16* __restrict__ Blo,
              float* __restrict__ C,
              __nv_bfloat16* __restrict__ Chi, __nv_bfloat16* __restrict__ Clo,
              int ldc, int K,
              const float* __restrict__ bias,
              const float* __restrict__ addm)
{
    extern __shared__ __nv_bfloat16 sm[];
    const uint32_t smb = smem_u32(sm);
    constexpr int NACC = NACC_OF<BM>();
    constexpr int WMW = BM/32;
    constexpr int WNW = 8/WMW;
    constexpr int NSPAN = 128/WNW;

    const int lane = threadIdx.x & 31, wid = threadIdx.x >> 5;
    const int wm = wid / WNW, wn = wid % WNW;
    const int tileM = blockIdx.y * BM;
    const int tileN = blockIdx.x * 128;

    float acc[2][NACC][4];
    #pragma unroll
    for (int i = 0; i < 2; i++)
        #pragma unroll
        for (int j = 0; j < NACC; j++)
            #pragma unroll
            for (int q = 0; q < 4; q++) acc[i][j][q] = 0.f;

    gemm_core<BM, NACC>(Ahi, Alo, lda, Bhi, Blo, K, tileM, tileN, smb, acc);

    #pragma unroll
    for (int mt = 0; mt < 2; mt++) {
        #pragma unroll
        for (int nt = 0; nt < NACC; nt++) {
            int gm = tileM + wm*32 + mt*16 + (lane >> 2);
            int gn = tileN + wn*NSPAN + nt*8 + (lane & 3)*2;
            #pragma unroll
            for (int half = 0; half < 2; half++) {
                int gmr = gm + half*8;
                float v0 = acc[mt][nt][half*2], v1 = acc[mt][nt][half*2+1];
                if (EPI == EPI_ADD) {
                    float2 am = *reinterpret_cast<const float2*>(addm + (size_t)gmr*ldc + gn);
                    v0 += bias[gn] + am.x; v1 += bias[gn+1] + am.y;
                } else if (EPI == EPI_GELU) {
                    float t0 = v0 + bias[gn], t1 = v1 + bias[gn+1];
                    v0 = 0.5f*t0*(1.f + erff(t0*0.70710678118654752f));
                    v1 = 0.5f*t1*(1.f + erff(t1*0.70710678118654752f));
                }
                if (SPLITOUT) {
                    uint32_t hi, lo;
                    split2(v0, v1, hi, lo);
                    *reinterpret_cast<uint32_t*>(Chi + (size_t)gmr*ldc + gn) = hi;
                    *reinterpret_cast<uint32_t*>(Clo + (size_t)gmr*ldc + gn) = lo;
                } else {
                    *reinterpret_cast<float2*>(C + (size_t)gmr*ldc + gn) = make_float2(v0, v1);
                }
            }
        }
    }
}

// ---------------------------------------------------------------------------
// Fused QKV GEMM: 640 CTAs (0..127 Q; 128..639 KV), BM=128
// ---------------------------------------------------------------------------
__global__ __launch_bounds__(256, 2)
void mma_qkv(const __nv_bfloat16* __restrict__ cxh, const __nv_bfloat16* __restrict__ cxl,
             const __nv_bfloat16* __restrict__ aeh, const __nv_bfloat16* __restrict__ ael,
             const __nv_bfloat16* __restrict__ wthi, const __nv_bfloat16* __restrict__ wtlo,
             __nv_bfloat16* __restrict__ qh, __nv_bfloat16* __restrict__ ql,
             __nv_bfloat16* __restrict__ kh, __nv_bfloat16* __restrict__ kl,
             __nv_bfloat16* __restrict__ vh, __nv_bfloat16* __restrict__ vl,
             const float* __restrict__ bq, const float* __restrict__ bk,
             const float* __restrict__ bv, const float* __restrict__ pos)
{
    extern __shared__ __nv_bfloat16 sm[];
    const uint32_t smb = smem_u32(sm);

    const int bz = blockIdx.x;
    const bool isQ = bz < 128;
    const __nv_bfloat16 *Ah, *Al, *Bh, *Bl;
    int tileM, tileN;
    if (isQ) {
        int nx = bz & 7, ny = bz >> 3;
        tileM = ny * 128; tileN = nx * 128;
        Ah = cxh; Al = cxl; Bh = wthi + WT_Q; Bl = wtlo + WT_Q;
    } else {
        int i = bz - 128;
        int nx = i & 15, ny = i >> 4;
        tileM = ny * 128; tileN = nx * 128;
        Ah = aeh; Al = ael; Bh = wthi + WT_K; Bl = wtlo + WT_K;
    }

    const int lane = threadIdx.x & 31, wid = threadIdx.x >> 5;
    const int wm = wid >> 1, wn = wid & 1;

    float acc[2][8][4];
    #pragma unroll
    for (int i = 0; i < 2; i++)
        #pragma unroll
        for (int j = 0; j < 8; j++)
            #pragma unroll
            for (int q = 0; q < 4; q++) acc[i][j][q] = 0.f;

    gemm_core<128, 8>(Ah, Al, NC, Bh, Bl, NC, tileM, tileN, smb, acc);

    #pragma unroll
    for (int mt = 0; mt < 2; mt++) {
        #pragma unroll
        for (int nt = 0; nt < 8; nt++) {
            int gm = tileM + wm*32 + mt*16 + (lane >> 2);
            int gn = tileN + wn*64 + nt*8 + (lane & 3)*2;
            #pragma unroll
            for (int half = 0; half < 2; half++) {
                int gmr = gm + half*8;
                float v0 = acc[mt][nt][half*2], v1 = acc[mt][nt][half*2+1];
                const float* pr = pos + (gmr % NS)*HD;
                uint32_t hi, lo;
                if (isQ) {
                    v0 = (v0 + bq[gn]   + pr[gn & (HD-1)])     * 0.125f;
                    v1 = (v1 + bq[gn+1] + pr[(gn+1) & (HD-1)]) * 0.125f;
                    split2(v0, v1, hi, lo);
                    *reinterpret_cast<uint32_t*>(qh + (size_t)gmr*NC + gn) = hi;
                    *reinterpret_cast<uint32_t*>(ql + (size_t)gmr*NC + gn) = lo;
                } else if (gn < NC) {
                    v0 = v0 + bk[gn]   + pr[gn & (HD-1)];
                    v1 = v1 + bk[gn+1] + pr[(gn+1) & (HD-1)];
                    split2(v0, v1, hi, lo);
                    *reinterpret_cast<uint32_t*>(kh + (size_t)gmr*NC + gn) = hi;
                    *reinterpret_cast<uint32_t*>(kl + (size_t)gmr*NC + gn) = lo;
                } else {
                    int gv = gn - NC;
                    v0 += bv[gv]; v1 += bv[gv+1];
                    split2(v0, v1, hi, lo);
                    *reinterpret_cast<uint32_t*>(vh + (size_t)gmr*NC + gv) = hi;
                    *reinterpret_cast<uint32_t*>(vl + (size_t)gmr*NC + gv) = lo;
                }
            }
        }
    }
}

// ---------------------------------------------------------------------------
// Flash attention v2 (round-12 layout, single barrier per tile)
// ---------------------------------------------------------------------------
constexpr int FLS  = 72;
constexpr int FQ_HI = 0;
constexpr int FQ_LO = 128*FLS;
constexpr int FKV   = 2*128*FLS;
constexpr int KVB   = 64*FLS;
constexpr int KVST  = 4*KVB;
constexpr int FLASH_SMEM = (2*128*FLS + 2*KVST) * 2;

__global__ __launch_bounds__(256, 2)
void flash_kernel(const __nv_bfloat16* __restrict__ qh, const __nv_bfloat16* __restrict__ ql,
                  const __nv_bfloat16* __restrict__ kh, const __nv_bfloat16* __restrict__ kl,
                  const __nv_bfloat16* __restrict__ vh, const __nv_bfloat16* __restrict__ vl,
                  __nv_bfloat16* __restrict__ oh, __nv_bfloat16* __restrict__ ol)
{
    extern __shared__ __nv_bfloat16 sf[];
    const uint32_t smb = smem_u32(sf);
    const int tid = threadIdx.x, lane = tid & 31, wid = tid >> 5;
    const int bh = blockIdx.y, b = bh >> 4, h = bh & 15;
    const int bx = blockIdx.x;
    const int q0 = bx * 128;
    const size_t qoff = (size_t)b*NS*NC   + h*HD;
    const size_t koff = (size_t)b*2*NS*NC + h*HD;

    const int sr = tid >> 2, sc0 = (tid & 3) * 16;

    // stage Q + first KV tile together
    {
        const int r = tid >> 1, c0 = (tid & 1) * 32;
        #pragma unroll
        for (int i = 0; i < 4; i++) {
            int cc = c0 + i*8;
            size_t ga = qoff + (size_t)(q0 + r)*NC + cc;
            uint32_t so = (r*FLS + cc) * 2;
            CP16(smb + FQ_HI*2 + so, qh + ga);
            CP16(smb + FQ_LO*2 + so, ql + ga);
        }
        uint32_t base = smb + (uint32_t)(FKV + 0*KVST)*2;
        #pragma unroll
        for (int i = 0; i < 2; i++) {
            int cc = sc0 + i*8;
            size_t ga = koff + (size_t)(0 + sr)*NC + cc;
            uint32_t so = (sr*FLS + cc) * 2;
            CP16(base + so,           kh + ga);
            CP16(base + KVB*2 + so,   kl + ga);
            CP16(base + 2*KVB*2 + so, vh + ga);
            CP16(base + 3*KVB*2 + so, vl + ga);
        }
        CP_COMMIT(); CP_WAIT0();
    }
    __syncthreads();

    const int arow = wid*16 + (lane & 15);
    const int half8 = (lane >> 4) << 3;
    uint32_t qhi4[4][4], qlo4[4][4];
    #pragma unroll
    for (int kc = 0; kc < 4; kc++) {
        uint32_t off = (arow*FLS + kc*16 + half8) * 2;
        ldm_x4(qhi4[kc], smb + FQ_HI*2 + off);
        ldm_x4(qlo4[kc], smb + FQ_LO*2 + off);
    }

    float om[8][4];
    #pragma unroll
    for (int i = 0; i < 8; i++)
        #pragma unroll
        for (int j = 0; j < 4; j++) om[i][j] = 0.f;
    float m_i0 = -1e30f, m_i1 = -1e30f, l_i0 = 0.f, l_i1 = 0.f;

    const int qrow0 = q0 + wid*16 + (lane >> 2);

    const int fe = 2*bx + 1;
    const int bs = 16 + 2*bx;
    constexpr int NT_ACT = 18;

    for (int it = 0; it < NT_ACT; it++) {
        const int kt = (it <= fe) ? it : (bs + (it - fe - 1));
        const int st = it & 1;

        if (it > 0) { CP_WAIT0(); __syncthreads(); }
        // issue-after-barrier: stage it+1 into st^1 (readers of st^1 finished)
        if (it + 1 < NT_ACT) {
            const int ktn = (it + 1 <= fe) ? (it + 1) : (bs + (it + 1 - fe - 1));
            const int kg0n = ktn * 64;
            uint32_t base = smb + (uint32_t)(FKV + (st ^ 1)*KVST)*2;
            #pragma unroll
            for (int i = 0; i < 2; i++) {
                int cc = sc0 + i*8;
                size_t ga = koff + (size_t)(kg0n + sr)*NC + cc;
                uint32_t so = (sr*FLS + cc) * 2;
                CP16(base + so,           kh + ga);
                CP16(base + KVB*2 + so,   kl + ga);
                CP16(base + 2*KVB*2 + so, vh + ga);
                CP16(base + 3*KVB*2 + so, vl + ga);
            }
            CP_COMMIT();
        }

        const uint32_t kvb = smb + (uint32_t)(FKV + st*KVST)*2;
        const int kg0 = kt * 64;
        const bool fwdh = kt < 16;
        const bool full = fwdh ? (kt <= 2*bx - 1) : (kt >= 18 + 2*bx);

        float s[8][4];
        #pragma unroll
        for (int i = 0; i < 8; i++)
            #pragma unroll
            for (int j = 0; j < 4; j++) s[i][j] = 0.f;
        #pragma unroll
        for (int kc = 0; kc < 4; kc++) {
            #pragma unroll
            for (int np0 = 0; np0 < 4; np0 += 2) {
                uint32_t bh4[2][4], bl4[2][4];
                #pragma unroll
                for (int p = 0; p < 2; p++) {
                    uint32_t off = (((np0+p)*16 + (lane & 15))*FLS + kc*16 + half8) * 2;
                    ldm_x4(bh4[p], kvb + off);
                    ldm_x4(bl4[p], kvb + KVB*2 + off);
                }
                #pragma unroll
                for (int p = 0; p < 2; p++) {
                    mma16816(s[(np0+p)*2],   qhi4[kc], bh4[p][0], bh4[p][2]);
                    mma16816(s[(np0+p)*2+1], qhi4[kc], bh4[p][1], bh4[p][3]);
                }
                #pragma unroll
                for (int p = 0; p < 2; p++) {
                    mma16816(s[(np0+p)*2],   qhi4[kc], bl4[p][0], bl4[p][2]);
                    mma16816(s[(np0+p)*2+1], qhi4[kc], bl4[p][1], bl4[p][3]);
                }
                #pragma unroll
                for (int p = 0; p < 2; p++) {
                    mma16816(s[(np0+p)*2],   qlo4[kc], bh4[p][0], bh4[p][2]);
                    mma16816(s[(np0+p)*2+1], qlo4[kc], bh4[p][1], bh4[p][3]);
                }
            }
        }

        if (!full) {
            #pragma unroll
            for (int nt = 0; nt < 8; nt++) {
                int kbase = kg0 + nt*8 + (lane & 3)*2;
                #pragma unroll
                for (int d = 0; d < 2; d++) {
                    int kidx = kbase + d;
                    bool ok0, ok1;
                    if (fwdh) { ok0 = (kidx <= qrow0); ok1 = (kidx <= qrow0 + 8); }
                    else      { int j = kidx - 1024; ok0 = (j >= qrow0); ok1 = (j >= qrow0 + 8); }
                    if (!ok0) s[nt][d]     = -1e30f;
                    if (!ok1) s[nt][d + 2] = -1e30f;
                }
            }
        }

        float mx0 = -1e30f, mx1 = -1e30f;
        #pragma unroll
        for (int nt = 0; nt < 8; nt++) {
            mx0 = fmaxf(mx0, fmaxf(s[nt][0], s[nt][1]));
            mx1 = fmaxf(mx1, fmaxf(s[nt][2], s[nt][3]));
        }
        mx0 = fmaxf(mx0, __shfl_xor_sync(0xffffffffu, mx0, 1));
        mx0 = fmaxf(mx0, __shfl_xor_sync(0xffffffffu, mx0, 2));
        mx1 = fmaxf(mx1, __shfl_xor_sync(0xffffffffu, mx1, 1));
        mx1 = fmaxf(mx1, __shfl_xor_sync(0xffffffffu, mx1, 2));
        float mn0 = fmaxf(m_i0, mx0), mn1 = fmaxf(m_i1, mx1);
        float sc0f = __expf(m_i0 - mn0), sc1f = __expf(m_i1 - mn1);
        m_i0 = mn0; m_i1 = mn1;
        float rs0 = 0.f, rs1 = 0.f;
        #pragma unroll
        for (int nt = 0; nt < 8; nt++) {
            s[nt][0] = __expf(s[nt][0] - mn0);
            s[nt][1] = __expf(s[nt][1] - mn0);
            s[nt][2] = __expf(s[nt][2] - mn1);
            s[nt][3] = __expf(s[nt][3] - mn1);
            rs0 += s[nt][0] + s[nt][1];
            rs1 += s[nt][2] + s[nt][3];
        }
        rs0 += __shfl_xor_sync(0xffffffffu, rs0, 1);
        rs0 += __shfl_xor_sync(0xffffffffu, rs0, 2);
        rs1 += __shfl_xor_sync(0xffffffffu, rs1, 1);
        rs1 += __shfl_xor_sync(0xffffffffu, rs1, 2);
        l_i0 = l_i0 * sc0f + rs0;
        l_i1 = l_i1 * sc1f + rs1;
        #pragma unroll
        for (int nt = 0; nt < 8; nt++) {
            om[nt][0] *= sc0f; om[nt][1] *= sc0f;
            om[nt][2] *= sc1f; om[nt][3] *= sc1f;
        }

        #pragma unroll
        for (int kc = 0; kc < 4; kc++) {
            uint32_t ph[4], pl[4];
            split2(s[2*kc][0],   s[2*kc][1],   ph[0], pl[0]);
            split2(s[2*kc][2],   s[2*kc][3],   ph[1], pl[1]);
            split2(s[2*kc+1][0], s[2*kc+1][1], ph[2], pl[2]);
            split2(s[2*kc+1][2], s[2*kc+1][3], ph[3], pl[3]);
            const int vm = lane >> 3, vr = lane & 7;
            #pragma unroll
            for (int hp0 = 0; hp0 < 4; hp0 += 2) {
                uint32_t vh4[2][4], vl4[2][4];
                #pragma unroll
                for (int p = 0; p < 2; p++) {
                    uint32_t vaddr = ((kc*16 + (vm & 1)*8 + vr)*FLS + (hp0+p)*16 + (vm >> 1)*8) * 2;
                    ldm_x4_t(vh4[p], kvb + 2*KVB*2 + vaddr);
                    ldm_x4_t(vl4[p], kvb + 3*KVB*2 + vaddr);
                }
                #pragma unroll
                for (int p = 0; p < 2; p++) {
                    mma16816(om[(hp0+p)*2],   ph, vh4[p][0], vh4[p][1]);
                    mma16816(om[(hp0+p)*2+1], ph, vh4[p][2], vh4[p][3]);
                }
                #pragma unroll
                for (int p = 0; p < 2; p++) {
                    mma16816(om[(hp0+p)*2],   pl, vh4[p][0], vh4[p][1]);
                    mma16816(om[(hp0+p)*2+1], pl, vh4[p][2], vh4[p][3]);
                }
                #pragma unroll
                for (int p = 0; p < 2; p++) {
                    mma16816(om[(hp0+p)*2],   ph, vl4[p][0], vl4[p][1]);
                    mma16816(om[(hp0+p)*2+1], ph, vl4[p][2], vl4[p][3]);
                }
            }
        }
        // no end-of-tile barrier
    }

    float il0 = 1.f / l_i0, il1 = 1.f / l_i1;
    #pragma unroll
    for (int nt = 0; nt < 8; nt++) {
        int hd = nt*8 + (lane & 3)*2;
        uint32_t hi, lo;
        split2(om[nt][0]*il0, om[nt][1]*il0, hi, lo);
        *reinterpret_cast<uint32_t*>(oh + qoff + (size_t)qrow0*NC + hd) = hi;
        *reinterpret_cast<uint32_t*>(ol + qoff + (size_t)qrow0*NC + hd) = lo;
        split2(om[nt][2]*il1, om[nt][3]*il1, hi, lo);
        *reinterpret_cast<uint32_t*>(oh + qoff + (size_t)(qrow0+8)*NC + hd) = hi;
        *reinterpret_cast<uint32_t*>(ol + qoff + (size_t)(qrow0+8)*NC + hd) = lo;
    }
}

// ---------------------------------------------------------------------------
// Block reduction + LN kernels
// ---------------------------------------------------------------------------
__device__ __forceinline__ float2 block_reduce_sum2(float a, float b) {
    __shared__ float sha[8], shb[8];
    #pragma unroll
    for (int o = 16; o > 0; o >>= 1) {
        a += __shfl_xor_sync(0xffffffffu, a, o);
        b += __shfl_xor_sync(0xffffffffu, b, o);
    }
    int lane = threadIdx.x & 31, w = threadIdx.x >> 5;
    __syncthreads();
    if (lane == 0) { sha[w] = a; shb[w] = b; }
    __syncthreads();
    a = sha[lane & 7]; b = shb[lane & 7];
    #pragma unroll
    for (int o = 4; o > 0; o >>= 1) {
        a += __shfl_xor_sync(0xffffffffu, a, o);
        b += __shfl_xor_sync(0xffffffffu, b, o);
    }
    return make_float2(a, b);
}

__device__ __forceinline__ void store_split(__nv_bfloat16* hi, __nv_bfloat16* lo,
                                            size_t idx, float y) {
    __nv_bfloat16 hv = __float2bfloat16_rn(y);
    hi[idx] = hv;
    lo[idx] = __float2bfloat16_rn(y - __bfloat162float(hv));
}

__global__ void ln_all(const float* __restrict__ fwd, const float* __restrict__ bwd,
                       const float* __restrict__ g, const float* __restrict__ bta,
                       float* __restrict__ comb,
                       __nv_bfloat16* __restrict__ cxh, __nv_bfloat16* __restrict__ cxl,
                       __nv_bfloat16* __restrict__ aeh, __nv_bfloat16* __restrict__ ael)
{
    int z = blockIdx.x;
    if (z < NB*NS) {
        int row = z;
        int b = row / NS, s = row % NS;
        const float* fp = fwd + ((size_t)b*(NS+1) + s) * NC;
        const float* rp = bwd + ((size_t)b*(NS+1) + s + 1) * NC;
        const float rs2 = 0.70710678118654752f;
        float vals[4];
        float sum = 0.f, sq = 0.f;
        #pragma unroll
        for (int t = 0; t < 4; t++) {
            int i = threadIdx.x + t*256;
            float c = (fp[i] + rp[i]) * rs2;
            vals[t] = c; sum += c; sq += c*c;
            comb[(size_t)row*NC + i] = c;
        }
        float2 r2 = block_reduce_sum2(sum, sq);
        float mean = r2.x * (1.f/NC);
        float var  = r2.y * (1.f/NC) - mean*mean;
        float rinv = rsqrtf(var + 1e-5f);
        #pragma unroll
        for (int t = 0; t < 4; t++) {
            int i = threadIdx.x + t*256;
            store_split(cxh, cxl, (size_t)row*NC + i, (vals[t] - mean) * rinv * g[i] + bta[i]);
        }
    } else {
        int row = z - NB*NS;
        int b = row / (2*NS), t = row % (2*NS);
        const float* src = (t < NS) ? fwd + ((size_t)b*(NS+1) + t) * NC
                                    : bwd + ((size_t)b*(NS+1) + (t - NS) + 1) * NC;
        float vals[4];
        float sum = 0.f, sq = 0.f;
        #pragma unroll
        for (int u = 0; u < 4; u++) {
            int i = threadIdx.x + u*256;
            float c = src[i];
            vals[u] = c; sum += c; sq += c*c;
        }
        float2 r2 = block_reduce_sum2(sum, sq);
        float mean = r2.x * (1.f/NC);
        float var  = r2.y * (1.f/NC) - mean*mean;
        float rinv = rsqrtf(var + 1e-5f);
        #pragma unroll
        for (int u = 0; u < 4; u++) {
            int i = threadIdx.x + u*256;
            store_split(aeh, ael, (size_t)row*NC + i, (vals[u] - mean) * rinv * g[i] + bta[i]);
        }
    }
}

__global__ void double_ln_kernel(const float* __restrict__ xin,
                                 const float* __restrict__ g2, const float* __restrict__ b2,
                                 const float* __restrict__ gm, const float* __restrict__ bm,
                                 __nv_bfloat16* __restrict__ hh, __nv_bfloat16* __restrict__ hl)
{
    int row = blockIdx.x;
    const float* xp = xin + (size_t)row*NC;
    float vals[4];
    float s = 0.f, sq = 0.f;
    #pragma unroll
    for (int t = 0; t < 4; t++) {
        int i = threadIdx.x + t*256;
        float vv = xp[i];
        vals[t] = vv; s += vv; sq += vv*vv;
    }
    float2 r2 = block_reduce_sum2(s, sq);
    float mean = r2.x * (1.f/NC);
    float var  = r2.y * (1.f/NC) - mean*mean;
    float rinv = rsqrtf(var + 1e-5f);
    s = 0.f; sq = 0.f;
    #pragma unroll
    for (int t = 0; t < 4; t++) {
        int i = threadIdx.x + t*256;
        float y = (vals[t] - mean) * rinv * g2[i] + b2[i];
        vals[t] = y; s += y; sq += y*y;
    }
    r2 = block_reduce_sum2(s, sq);
    mean = r2.x * (1.f/NC);
    var  = r2.y * (1.f/NC) - mean*mean;
    rinv = rsqrtf(var + 1e-5f);
    #pragma unroll
    for (int t = 0; t < 4; t++) {
        int i = threadIdx.x + t*256;
        store_split(hh, hl, (size_t)row*NC + i, (vals[t] - mean) * rinv * gm[i] + bm[i]);
    }
}

// ---------------------------------------------------------------------------
// Launch
// ---------------------------------------------------------------------------
extern "C" void kernel_launch(void* const* d_in, const int* in_sizes, int n_in,
                              void* d_out, int out_size)
{
    (void)in_sizes; (void)n_in; (void)out_size;
    const float* fwd  = (const float*)d_in[0];
    const float* bwd  = (const float*)d_in[1];
    const float* pos  = (const float*)d_in[2];
    const float* ln1g = (const float*)d_in[3];
    const float* ln1b = (const float*)d_in[4];
    const float* Wq   = (const float*)d_in[5];
    const float* bq   = (const float*)d_in[6];
    const float* Wk   = (const float*)d_in[7];
    const float* bk   = (const float*)d_in[8];
    const float* Wv   = (const float*)d_in[9];
    const float* bv   = (const float*)d_in[10];
    const float* Wo   = (const float*)d_in[11];
    const float* bo   = (const float*)d_in[12];
    const float* ln2g = (const float*)d_in[13];
    const float* ln2b = (const float*)d_in[14];
    const float* mlpg = (const float*)d_in[15];
    const float* mlpb = (const float*)d_in[16];
    const float* W1   = (const float*)d_in[17];
    const float* b1   = (const float*)d_in[18];
    const float* W2   = (const float*)d_in[19];
    const float* b2   = (const float*)d_in[20];
    float* out = (float*)d_out;

    float *comb, *x;
    __nv_bfloat16 *cxh,*cxl,*aeh,*ael,*qh,*ql,*kh,*kl,*vh,*vl,*oh,*ol,*hh,*hl,*m1h,*m1l;
    __nv_bfloat16 *wthi, *wtlo;
    cudaGetSymbolAddress((void**)&comb, g_comb);
    cudaGetSymbolAddress((void**)&x,    g_x);
    cudaGetSymbolAddress((void**)&cxh,  g_cxh);  cudaGetSymbolAddress((void**)&cxl, g_cxl);
    cudaGetSymbolAddress((void**)&aeh,  g_aeh);  cudaGetSymbolAddress((void**)&ael, g_ael);
    cudaGetSymbolAddress((void**)&qh,   g_qh);   cudaGetSymbolAddress((void**)&ql,  g_ql);
    cudaGetSymbolAddress((void**)&kh,   g_kh);   cudaGetSymbolAddress((void**)&kl,  g_kl);
    cudaGetSymbolAddress((void**)&vh,   g_vh);   cudaGetSymbolAddress((void**)&vl,  g_vl);
    cudaGetSymbolAddress((void**)&oh,   g_oh);   cudaGetSymbolAddress((void**)&ol,  g_ol);
    cudaGetSymbolAddress((void**)&hh,   g_hh);   cudaGetSymbolAddress((void**)&hl,  g_hl);
    cudaGetSymbolAddress((void**)&m1h,  g_m1h);  cudaGetSymbolAddress((void**)&m1l, g_m1l);
    cudaGetSymbolAddress((void**)&wthi, g_wthi);
    cudaGetSymbolAddress((void**)&wtlo, g_wtlo);

    constexpr int SM128 = SMEM_OF<128>();
    constexpr int SM64  = SMEM_OF<64>();
    cudaFuncSetAttribute(mma_qkv,                      cudaFuncAttributeMaxDynamicSharedMemorySize, SM128);
    cudaFuncSetAttribute(mma_gemm<64,EPI_ADD,false>,   cudaFuncAttributeMaxDynamicSharedMemorySize, SM64);
    cudaFuncSetAttribute(mma_gemm<128,EPI_GELU,true>,  cudaFuncAttributeMaxDynamicSharedMemorySize, SM128);
    cudaFuncSetAttribute(flash_kernel,                 cudaFuncAttributeMaxDynamicSharedMemorySize, FLASH_SMEM);

    // 1: all weight transforms, one launch
    wt_split_all<<<12288, dim3(32, 8)>>>(Wq, Wk, Wv, Wo, W1, W2, wthi, wtlo);

    // 2: both LayerNorms, one launch
    ln_all<<<NB*NS + NB*2*NS, 256>>>(fwd, bwd, ln1g, ln1b, comb, cxh, cxl, aeh, ael);

    // 3: fused Q+K+V projections (640 CTAs, BM=128)
    mma_qkv<<<640, 256, SM128>>>(cxh, cxl, aeh, ael, wthi, wtlo,
                                 qh, ql, kh, kl, vh, vl, bq, bk, bv, pos);

    // 4: fused flash attention
    flash_kernel<<<dim3(NS/128, NB*NH), 256, FLASH_SMEM>>>(qh, ql, kh, kl, vh, vl, oh, ol);

    // 5: x = comb + (o @ Wo + bo)   [BM=64 -> 256 CTAs]
    mma_gemm<64,EPI_ADD,false><<<dim3(NC/128, (NB*NS)/64), 256, SM64>>>(
        oh, ol, NC, wthi + WT_O, wtlo + WT_O, x, nullptr, nullptr, NC, NC, bo, comb);

    // 6: h = LN(LN(x))
    double_ln_kernel<<<NB*NS, 256>>>(x, ln2g, ln2b, mlpg, mlpb, hh, hl);

    // 7: m1 = gelu(h @ W1 + b1)   [BM=128 -> 512 CTAs]
    mma_gemm<128,EPI_GELU,true><<<dim3((NE*NC)/128, (NB*NS)/128), 256, SM128>>>(
        hh, hl, NC, wthi + WT_1, wtlo + WT_1, nullptr, m1h, m1l, NE*NC, NC, b1, nullptr);

    // 8: out = x + (m1 @ W2 + b2)   [BM=64 -> 256 CTAs]
    mma_gemm<64,EPI_ADD,false><<<dim3(NC/128, (NB*NS)/64), 256, SM64>>>(
        m1h, m1l, NE*NC, wthi + WT_2, wtlo + WT_2, out, nullptr, nullptr, NC, NE*NC, b2, x);
}

// round 15
// speedup vs baseline: 1.0103x; 1.0070x over previous
#include <cuda_runtime.h>
#include <cuda_bf16.h>
#include <math.h>
#include <float.h>
#include <stdint.h>

// Problem constants
constexpr int NB = 2;
constexpr int NS = 1024;
constexpr int NC = 1024;
constexpr int NH = 16;
constexpr int HD = 64;
constexpr int NE = 4;

// ---------------------------------------------------------------------------
// Scratch (device globals)
// ---------------------------------------------------------------------------
__device__ float g_comb[NB*NS*NC];
__device__ float g_x   [NB*NS*NC];

__device__ __nv_bfloat16 g_cxh[NB*NS*NC],    g_cxl[NB*NS*NC];
__device__ __nv_bfloat16 g_aeh[NB*2*NS*NC],  g_ael[NB*2*NS*NC];
__device__ __nv_bfloat16 g_qh [NB*NS*NC],    g_ql [NB*NS*NC];
__device__ __nv_bfloat16 g_kh [NB*2*NS*NC],  g_kl [NB*2*NS*NC];
__device__ __nv_bfloat16 g_vh [NB*2*NS*NC],  g_vl [NB*2*NS*NC];
__device__ __nv_bfloat16 g_oh [NB*NS*NC],    g_ol [NB*NS*NC];
__device__ __nv_bfloat16 g_hh [NB*NS*NC],    g_hl [NB*NS*NC];
__device__ __nv_bfloat16 g_m1h[NB*NS*NE*NC], g_m1l[NB*NS*NE*NC];

__device__ __nv_bfloat16 g_wthi[12u<<20];
__device__ __nv_bfloat16 g_wtlo[12u<<20];
constexpr size_t WT_Q = 0;
constexpr size_t WT_K = (size_t)1<<20;
constexpr size_t WT_V = (size_t)2<<20;
constexpr size_t WT_O = (size_t)3<<20;
constexpr size_t WT_1 = (size_t)4<<20;
constexpr size_t WT_2 = (size_t)8<<20;

// ---------------------------------------------------------------------------
// Helpers
// ---------------------------------------------------------------------------
__device__ __forceinline__ uint32_t smem_u32(const void* p) {
    uint32_t a;
    asm("{ .reg .u64 t; cvta.to.shared.u64 t, %1; cvt.u32.u64 %0, t; }" : "=r"(a) : "l"(p));
    return a;
}
__device__ __forceinline__ uint32_t pack_bf(float a, float b) {
    __nv_bfloat162 h = __floats2bfloat162_rn(a, b);
    return *reinterpret_cast<uint32_t*>(&h);
}
__device__ __forceinline__ void split2(float a, float b, uint32_t& hi, uint32_t& lo) {
    __nv_bfloat16 ha = __float2bfloat16_rn(a);
    __nv_bfloat16 hb = __float2bfloat16_rn(b);
    hi = pack_bf(a, b);
    lo = pack_bf(a - __bfloat162float(ha), b - __bfloat162float(hb));
}
__device__ __forceinline__ void ldm_x4(uint32_t* r, uint32_t addr) {
    asm volatile("ldmatrix.sync.aligned.m8n8.x4.shared.b16 {%0,%1,%2,%3}, [%4];"
        : "=r"(r[0]), "=r"(r[1]), "=r"(r[2]), "=r"(r[3]) : "r"(addr));
}
__device__ __forceinline__ void ldm_x4_t(uint32_t* r, uint32_t addr) {
    asm volatile("ldmatrix.sync.aligned.m8n8.x4.trans.shared.b16 {%0,%1,%2,%3}, [%4];"
        : "=r"(r[0]), "=r"(r[1]), "=r"(r[2]), "=r"(r[3]) : "r"(addr));
}
__device__ __forceinline__ void mma16816(float* d, const uint32_t* a, uint32_t b0, uint32_t b1) {
    asm volatile(
        "mma.sync.aligned.m16n8k16.row.col.f32.bf16.bf16.f32 "
        "{%0,%1,%2,%3}, {%4,%5,%6,%7}, {%8,%9}, {%0,%1,%2,%3};"
        : "+f"(d[0]), "+f"(d[1]), "+f"(d[2]), "+f"(d[3])
        : "r"(a[0]), "r"(a[1]), "r"(a[2]), "r"(a[3]), "r"(b0), "r"(b1));
}
#define CP16(dst, src) \
    asm volatile("cp.async.cg.shared.global [%0], [%1], 16;" :: "r"(dst), "l"(src))
#define CP_COMMIT() asm volatile("cp.async.commit_group;")
#define CP_WAIT0()  asm volatile("cp.async.wait_group 0;")
#define CP_WAIT1()  asm volatile("cp.async.wait_group 1;")

// ---------------------------------------------------------------------------
// Merged weight transform
// ---------------------------------------------------------------------------
__global__ void wt_split_all(const float* __restrict__ Wq, const float* __restrict__ Wk,
                             const float* __restrict__ Wv, const float* __restrict__ Wo,
                             const float* __restrict__ W1, const float* __restrict__ W2,
                             __nv_bfloat16* __restrict__ hi_base,
                             __nv_bfloat16* __restrict__ lo_base)
{
    int z = blockIdx.x;
    const float* W; size_t off; int K, N, bx, by;
    if (z < 1024)      { W = Wq; off = WT_Q; K = 1024; N = 1024; bx = z & 31;  by = z >> 5; }
    else if (z < 2048) { int i = z - 1024; W = Wk; off = WT_K; K = 1024; N = 1024; bx = i & 31; by = i >> 5; }
    else if (z < 3072) { int i = z - 2048; W = Wv; off = WT_V; K = 1024; N = 1024; bx = i & 31; by = i >> 5; }
    else if (z < 4096) { int i = z - 3072; W = Wo; off = WT_O; K = 1024; N = 1024; bx = i & 31; by = i >> 5; }
    else if (z < 8192) { int i = z - 4096; W = W1; off = WT_1; K = 1024; N = 4096; bx = i & 127; by = i >> 7; }
    else               { int i = z - 8192; W = W2; off = WT_2; K = 4096; N = 1024; bx = i & 31;  by = i >> 5; }
    __nv_bfloat16* hi = hi_base + off;
    __nv_bfloat16* lo = lo_base + off;

    __shared__ float t[32][33];
    int n0 = bx * 32, k0 = by * 32;
    #pragma unroll
    for (int i = 0; i < 4; i++) {
        int k = k0 + threadIdx.y + 8*i;
        t[threadIdx.y + 8*i][threadIdx.x] = W[(size_t)k*N + n0 + threadIdx.x];
    }
    __syncthreads();
    #pragma unroll
    for (int i = 0; i < 4; i++) {
        int n = n0 + threadIdx.y + 8*i;
        int k = k0 + threadIdx.x;
        float v = t[threadIdx.x][threadIdx.y + 8*i];
        __nv_bfloat16 h = __float2bfloat16_rn(v);
        __nv_bfloat16 l = __float2bfloat16_rn(v - __bfloat162float(h));
        hi[(size_t)n*K + k] = h;
        lo[(size_t)n*K + k] = l;
    }
}

// ---------------------------------------------------------------------------
// GEMM core (round-12 structure: 2-stage, stage-before-wait, 2 barriers/chunk)
// ---------------------------------------------------------------------------
constexpr int BLDS = 40;

template<int BM> __host__ __device__ constexpr int NACC_OF() { return 2 * ((128 / (8 / (BM/32))) / 16); }
template<int BM> __host__ __device__ constexpr int SSZ_OF()  { return 2*BM*BLDS + 2*128*BLDS; }
template<int BM> __host__ __device__ constexpr int SMEM_OF() { return 2 * SSZ_OF<BM>() * 2; }

template<int BM, int NACC>
__device__ __forceinline__ void gemm_core(
    const __nv_bfloat16* __restrict__ Ahi, const __nv_bfloat16* __restrict__ Alo, int lda,
    const __nv_bfloat16* __restrict__ Bhi, const __nv_bfloat16* __restrict__ Blo, int K,
    int tileM, int tileN, uint32_t smb, float (&acc)[2][NACC][4])
{
    constexpr int WMW = BM/32;
    constexpr int WNW = 8/WMW;
    constexpr int NSPAN = 128/WNW;
    constexpr int NTP = NSPAN/16;
    static_assert(NACC == 2*NTP, "acc shape");
    static_assert((NTP & 1) == 0, "NTP even");
    constexpr int ASZ = BM*BLDS;
    constexpr int BSZ = 128*BLDS;
    constexpr int SSZ = 2*ASZ + 2*BSZ;

    const int tid = threadIdx.x, lane = tid & 31, wid = tid >> 5;
    const int wm = wid / WNW, wn = wid % WNW;
    const int a_row = wm*32 + (lane & 15);
    const int b_row = wn*NSPAN + (lane & 15);
    const int half8 = (lane >> 4) << 3;

    const int sr0 = tid >> 2, sc0 = (tid & 3) * 8;
    const int nch = K >> 5;

    // prologue: stage 0
    {
        #pragma unroll
        for (int p = 0; p < BM/64; p++) {
            int r = sr0 + p*64;
            uint32_t so = (r*BLDS + sc0) * 2;
            size_t ga = (size_t)(tileM + r)*lda + sc0;
            CP16(smb + so,           Ahi + ga);
            CP16(smb + ASZ*2 + so,   Alo + ga);
        }
        #pragma unroll
        for (int p = 0; p < 2; p++) {
            int r = sr0 + p*64;
            uint32_t so = (r*BLDS + sc0) * 2;
            size_t ga = (size_t)(tileN + r)*K + sc0;
            CP16(smb + 2*ASZ*2 + so,         Bhi + ga);
            CP16(smb + (2*ASZ+BSZ)*2 + so,   Blo + ga);
        }
        CP_COMMIT();
    }

    for (int c = 0; c < nch; c++) {
        const int st = c & 1;
        if (c + 1 < nch) {
            const int k0 = (c + 1) << 5;
            const uint32_t sb2 = smb + (uint32_t)((st ^ 1) * SSZ * 2);
            #pragma unroll
            for (int p = 0; p < BM/64; p++) {
                int r = sr0 + p*64;
                uint32_t so = (r*BLDS + sc0) * 2;
                size_t ga = (size_t)(tileM + r)*lda + k0 + sc0;
                CP16(sb2 + so,         Ahi + ga);
                CP16(sb2 + ASZ*2 + so, Alo + ga);
            }
            #pragma unroll
            for (int p = 0; p < 2; p++) {
                int r = sr0 + p*64;
                uint32_t so = (r*BLDS + sc0) * 2;
                size_t ga = (size_t)(tileN + r)*K + k0 + sc0;
                CP16(sb2 + 2*ASZ*2 + so,       Bhi + ga);
                CP16(sb2 + (2*ASZ+BSZ)*2 + so, Blo + ga);
            }
            CP_COMMIT();
            CP_WAIT1();
        } else {
            CP_WAIT0();
        }
        __syncthreads();

        const uint32_t sbase = smb + (uint32_t)(st * SSZ * 2);
        #pragma unroll
        for (int ks = 0; ks < 32; ks += 16) {
            uint32_t ahi[2][4], alo[2][4];
            #pragma unroll
            for (int mt = 0; mt < 2; mt++) {
                uint32_t off = ((a_row + mt*16)*BLDS + ks + half8) * 2;
                ldm_x4(ahi[mt], sbase + off);
                ldm_x4(alo[mt], sbase + ASZ*2 + off);
            }
            #pragma unroll
            for (int np0 = 0; np0 < NTP; np0 += 2) {
                uint32_t bh[2][4], bl[2][4];
                #pragma unroll
                for (int p = 0; p < 2; p++) {
                    uint32_t off = ((b_row + (np0+p)*16)*BLDS + ks + half8) * 2;
                    ldm_x4(bh[p], sbase + 2*ASZ*2 + off);
                    ldm_x4(bl[p], sbase + (2*ASZ+BSZ)*2 + off);
                }
                #pragma unroll
                for (int p = 0; p < 2; p++)
                    #pragma unroll
                    for (int mt = 0; mt < 2; mt++) {
                        mma16816(acc[mt][(np0+p)*2],   ahi[mt], bh[p][0], bh[p][2]);
                        mma16816(acc[mt][(np0+p)*2+1], ahi[mt], bh[p][1], bh[p][3]);
                    }
                #pragma unroll
                for (int p = 0; p < 2; p++)
                    #pragma unroll
                    for (int mt = 0; mt < 2; mt++) {
                        mma16816(acc[mt][(np0+p)*2],   ahi[mt], bl[p][0], bl[p][2]);
                        mma16816(acc[mt][(np0+p)*2+1], ahi[mt], bl[p][1], bl[p][3]);
                    }
                #pragma unroll
                for (int p = 0; p < 2; p++)
                    #pragma unroll
                    for (int mt = 0; mt < 2; mt++) {
                        mma16816(acc[mt][(np0+p)*2],   alo[mt], bh[p][0], bh[p][2]);
                        mma16816(acc[mt][(np0+p)*2+1], alo[mt], bh[p][1], bh[p][3]);
                    }
            }
        }
        __syncthreads();
    }
}

// ---------------------------------------------------------------------------
// Generic GEMM kernel (Wo / W1 / W2 paths)
// ---------------------------------------------------------------------------
enum { EPI_ADD = 3, EPI_GELU = 4 };

template<int BM, int EPI, bool SPLITOUT>
__global__ __launch_bounds__(256, 2)
void mma_gemm(const __nv_bfloat16* __restrict__ Ahi, const __nv_bfloat16* __restrict__ Alo,
              int lda,
              const __nv_bfloat16* __restrict__ Bhi, const __nv_bfloat16* __restrict__ Blo,
              float* __restrict__ C,
              __nv_bfloat16* __restrict__ Chi, __nv_bfloat16* __restrict__ Clo,
              int ldc, int K,
              const float* __restrict__ bias,
              const float* __restrict__ addm)
{
    extern __shared__ __nv_bfloat16 sm[];
    const uint32_t smb = smem_u32(sm);
    constexpr int NACC = NACC_OF<BM>();
    constexpr int WMW = BM/32;
    constexpr int WNW = 8/WMW;
    constexpr int NSPAN = 128/WNW;

    const int lane = threadIdx.x & 31, wid = threadIdx.x >> 5;
    const int wm = wid / WNW, wn = wid % WNW;
    const int tileM = blockIdx.y * BM;
    const int tileN = blockIdx.x * 128;

    float acc[2][NACC][4];
    #pragma unroll
    for (int i = 0; i < 2; i++)
        #pragma unroll
        for (int j = 0; j < NACC; j++)
            #pragma unroll
            for (int q = 0; q < 4; q++) acc[i][j][q] = 0.f;

    gemm_core<BM, NACC>(Ahi, Alo, lda, Bhi, Blo, K, tileM, tileN, smb, acc);

    #pragma unroll
    for (int mt = 0; mt < 2; mt++) {
        #pragma unroll
        for (int nt = 0; nt < NACC; nt++) {
            int gm = tileM + wm*32 + mt*16 + (lane >> 2);
            int gn = tileN + wn*NSPAN + nt*8 + (lane & 3)*2;
            #pragma unroll
            for (int half = 0; half < 2; half++) {
                int gmr = gm + half*8;
                float v0 = acc[mt][nt][half*2], v1 = acc[mt][nt][half*2+1];
                if (EPI == EPI_ADD) {
                    float2 am = *reinterpret_cast<const float2*>(addm + (size_t)gmr*ldc + gn);
                    v0 += bias[gn] + am.x; v1 += bias[gn+1] + am.y;
                } else if (EPI == EPI_GELU) {
                    float t0 = v0 + bias[gn], t1 = v1 + bias[gn+1];
                    v0 = 0.5f*t0*(1.f + erff(t0*0.70710678118654752f));
                    v1 = 0.5f*t1*(1.f + erff(t1*0.70710678118654752f));
                }
                if (SPLITOUT) {
                    uint32_t hi, lo;
                    split2(v0, v1, hi, lo);
                    *reinterpret_cast<uint32_t*>(Chi + (size_t)gmr*ldc + gn) = hi;
                    *reinterpret_cast<uint32_t*>(Clo + (size_t)gmr*ldc + gn) = lo;
                } else {
                    *reinterpret_cast<float2*>(C + (size_t)gmr*ldc + gn) = make_float2(v0, v1);
                }
            }
        }
    }
}

// ---------------------------------------------------------------------------
// Fused QKV GEMM: 640 CTAs (0..127 Q; 128..639 KV), BM=128
// ---------------------------------------------------------------------------
__global__ __launch_bounds__(256, 2)
void mma_qkv(const __nv_bfloat16* __restrict__ cxh, const __nv_bfloat16* __restrict__ cxl,
             const __nv_bfloat16* __restrict__ aeh, const __nv_bfloat16* __restrict__ ael,
             const __nv_bfloat16* __restrict__ wthi, const __nv_bfloat16* __restrict__ wtlo,
             __nv_bfloat16* __restrict__ qh, __nv_bfloat16* __restrict__ ql,
             __nv_bfloat16* __restrict__ kh, __nv_bfloat16* __restrict__ kl,
             __nv_bfloat16* __restrict__ vh, __nv_bfloat16* __restrict__ vl,
             const float* __restrict__ bq, const float* __restrict__ bk,
             const float* __restrict__ bv, const float* __restrict__ pos)
{
    extern __shared__ __nv_bfloat16 sm[];
    const uint32_t smb = smem_u32(sm);

    const int bz = blockIdx.x;
    const bool isQ = bz < 128;
    const __nv_bfloat16 *Ah, *Al, *Bh, *Bl;
    int tileM, tileN;
    if (isQ) {
        int nx = bz & 7, ny = bz >> 3;
        tileM = ny * 128; tileN = nx * 128;
        Ah = cxh; Al = cxl; Bh = wthi + WT_Q; Bl = wtlo + WT_Q;
    } else {
        int i = bz - 128;
        int nx = i & 15, ny = i >> 4;
        tileM = ny * 128; tileN = nx * 128;
        Ah = aeh; Al = ael; Bh = wthi + WT_K; Bl = wtlo + WT_K;
    }

    const int lane = threadIdx.x & 31, wid = threadIdx.x >> 5;
    const int wm = wid >> 1, wn = wid & 1;

    float acc[2][8][4];
    #pragma unroll
    for (int i = 0; i < 2; i++)
        #pragma unroll
        for (int j = 0; j < 8; j++)
            #pragma unroll
            for (int q = 0; q < 4; q++) acc[i][j][q] = 0.f;

    gemm_core<128, 8>(Ah, Al, NC, Bh, Bl, NC, tileM, tileN, smb, acc);

    #pragma unroll
    for (int mt = 0; mt < 2; mt++) {
        #pragma unroll
        for (int nt = 0; nt < 8; nt++) {
            int gm = tileM + wm*32 + mt*16 + (lane >> 2);
            int gn = tileN + wn*64 + nt*8 + (lane & 3)*2;
            #pragma unroll
            for (int half = 0; half < 2; half++) {
                int gmr = gm + half*8;
                float v0 = acc[mt][nt][half*2], v1 = acc[mt][nt][half*2+1];
                const float* pr = pos + (gmr % NS)*HD;
                uint32_t hi, lo;
                if (isQ) {
                    v0 = (v0 + bq[gn]   + pr[gn & (HD-1)])     * 0.125f;
                    v1 = (v1 + bq[gn+1] + pr[(gn+1) & (HD-1)]) * 0.125f;
                    split2(v0, v1, hi, lo);
                    *reinterpret_cast<uint32_t*>(qh + (size_t)gmr*NC + gn) = hi;
                    *reinterpret_cast<uint32_t*>(ql + (size_t)gmr*NC + gn) = lo;
                } else if (gn < NC) {
                    v0 = v0 + bk[gn]   + pr[gn & (HD-1)];
                    v1 = v1 + bk[gn+1] + pr[(gn+1) & (HD-1)];
                    split2(v0, v1, hi, lo);
                    *reinterpret_cast<uint32_t*>(kh + (size_t)gmr*NC + gn) = hi;
                    *reinterpret_cast<uint32_t*>(kl + (size_t)gmr*NC + gn) = lo;
                } else {
                    int gv = gn - NC;
                    v0 += bv[gv]; v1 += bv[gv+1];
                    split2(v0, v1, hi, lo);
                    *reinterpret_cast<uint32_t*>(vh + (size_t)gmr*NC + gv) = hi;
                    *reinterpret_cast<uint32_t*>(vl + (size_t)gmr*NC + gv) = lo;
                }
            }
        }
    }
}

// ---------------------------------------------------------------------------
// Flash attention v3: Q smem region reused as KV stage A after frag loads.
// FLASH_SMEM halved -> solid 2 CTAs/SM residency.
// ---------------------------------------------------------------------------
constexpr int FLS  = 72;
constexpr int FQ_HI = 0;                  // elems; Q hi: 128 x FLS
constexpr int FQ_LO = 128*FLS;            // 9216
constexpr int KVB   = 64*FLS;             // 4608 elems per K/V term buffer
constexpr int KVST  = 4*KVB;              // 18432 elems per stage
constexpr int STAGE_A = 0;                // overlaps Q region (reused)
constexpr int STAGE_B = KVST;             // 18432
constexpr int FLASH_SMEM = 2*KVST*2;      // 73728 bytes

__global__ __launch_bounds__(256, 2)
void flash_kernel(const __nv_bfloat16* __restrict__ qh, const __nv_bfloat16* __restrict__ ql,
                  const __nv_bfloat16* __restrict__ kh, const __nv_bfloat16* __restrict__ kl,
                  const __nv_bfloat16* __restrict__ vh, const __nv_bfloat16* __restrict__ vl,
                  __nv_bfloat16* __restrict__ oh, __nv_bfloat16* __restrict__ ol)
{
    extern __shared__ __nv_bfloat16 sf[];
    const uint32_t smb = smem_u32(sf);
    const int tid = threadIdx.x, lane = tid & 31, wid = tid >> 5;
    const int bh = blockIdx.y, b = bh >> 4, h = bh & 15;
    const int bx = blockIdx.x;
    const int q0 = bx * 128;
    const size_t qoff = (size_t)b*NS*NC   + h*HD;
    const size_t koff = (size_t)b*2*NS*NC + h*HD;

    const int sr = tid >> 2, sc0 = (tid & 3) * 16;

    // prologue: stage Q (into region that later becomes stage A) + KV tile 0 (stage B)
    {
        const int r = tid >> 1, c0 = (tid & 1) * 32;
        #pragma unroll
        for (int i = 0; i < 4; i++) {
            int cc = c0 + i*8;
            size_t ga = qoff + (size_t)(q0 + r)*NC + cc;
            uint32_t so = (r*FLS + cc) * 2;
            CP16(smb + FQ_HI*2 + so, qh + ga);
            CP16(smb + FQ_LO*2 + so, ql + ga);
        }
        uint32_t base = smb + (uint32_t)STAGE_B*2;
        #pragma unroll
        for (int i = 0; i < 2; i++) {
            int cc = sc0 + i*8;
            size_t ga = koff + (size_t)(0 + sr)*NC + cc;
            uint32_t so = (sr*FLS + cc) * 2;
            CP16(base + so,           kh + ga);
            CP16(base + KVB*2 + so,   kl + ga);
            CP16(base + 2*KVB*2 + so, vh + ga);
            CP16(base + 3*KVB*2 + so, vl + ga);
        }
        CP_COMMIT(); CP_WAIT0();
    }
    __syncthreads();

    const int arow = wid*16 + (lane & 15);
    const int half8 = (lane >> 4) << 3;
    uint32_t qhi4[4][4], qlo4[4][4];
    #pragma unroll
    for (int kc = 0; kc < 4; kc++) {
        uint32_t off = (arow*FLS + kc*16 + half8) * 2;
        ldm_x4(qhi4[kc], smb + FQ_HI*2 + off);
        ldm_x4(qlo4[kc], smb + FQ_LO*2 + off);
    }
    // fence Q-fragment reads before any warp overwrites the Q region (stage A)
    __syncthreads();

    float om[8][4];
    #pragma unroll
    for (int i = 0; i < 8; i++)
        #pragma unroll
        for (int j = 0; j < 4; j++) om[i][j] = 0.f;
    float m_i0 = -1e30f, m_i1 = -1e30f, l_i0 = 0.f, l_i1 = 0.f;

    const int qrow0 = q0 + wid*16 + (lane >> 2);

    const int fe = 2*bx + 1;
    const int bs = 16 + 2*bx;
    constexpr int NT_ACT = 18;

    for (int it = 0; it < NT_ACT; it++) {
        const int kt = (it <= fe) ? it : (bs + (it - fe - 1));
        // tile it lives in stage: even -> B, odd -> A
        const uint32_t cur_base  = (it & 1) ? (uint32_t)STAGE_A : (uint32_t)STAGE_B;
        const uint32_t next_base = (it & 1) ? (uint32_t)STAGE_B : (uint32_t)STAGE_A;

        if (it + 1 < NT_ACT) {
            const int ktn = (it + 1 <= fe) ? (it + 1) : (bs + (it + 1 - fe - 1));
            const int kg0n = ktn * 64;
            uint32_t base = smb + next_base*2;
            #pragma unroll
            for (int i = 0; i < 2; i++) {
                int cc = sc0 + i*8;
                size_t ga = koff + (size_t)(kg0n + sr)*NC + cc;
                uint32_t so = (sr*FLS + cc) * 2;
                CP16(base + so,           kh + ga);
                CP16(base + KVB*2 + so,   kl + ga);
                CP16(base + 2*KVB*2 + so, vh + ga);
                CP16(base + 3*KVB*2 + so, vl + ga);
            }
            CP_COMMIT();
            CP_WAIT1();
        } else {
            CP_WAIT0();
        }
        __syncthreads();

        const uint32_t kvb = smb + cur_base*2;
        const int kg0 = kt * 64;
        const bool fwdh = kt < 16;
        const bool full = fwdh ? (kt <= 2*bx - 1) : (kt >= 18 + 2*bx);

        float s[8][4];
        #pragma unroll
        for (int i = 0; i < 8; i++)
            #pragma unroll
            for (int j = 0; j < 4; j++) s[i][j] = 0.f;
        #pragma unroll
        for (int kc = 0; kc < 4; kc++) {
            #pragma unroll
            for (int np0 = 0; np0 < 4; np0 += 2) {
                uint32_t bh4[2][4], bl4[2][4];
                #pragma unroll
                for (int p = 0; p < 2; p++) {
                    uint32_t off = (((np0+p)*16 + (lane & 15))*FLS + kc*16 + half8) * 2;
                    ldm_x4(bh4[p], kvb + off);
                    ldm_x4(bl4[p], kvb + KVB*2 + off);
                }
                #pragma unroll
                for (int p = 0; p < 2; p++) {
                    mma16816(s[(np0+p)*2],   qhi4[kc], bh4[p][0], bh4[p][2]);
                    mma16816(s[(np0+p)*2+1], qhi4[kc], bh4[p][1], bh4[p][3]);
                }
                #pragma unroll
                for (int p = 0; p < 2; p++) {
                    mma16816(s[(np0+p)*2],   qhi4[kc], bl4[p][0], bl4[p][2]);
                    mma16816(s[(np0+p)*2+1], qhi4[kc], bl4[p][1], bl4[p][3]);
                }
                #pragma unroll
                for (int p = 0; p < 2; p++) {
                    mma16816(s[(np0+p)*2],   qlo4[kc], bh4[p][0], bh4[p][2]);
                    mma16816(s[(np0+p)*2+1], qlo4[kc], bh4[p][1], bh4[p][3]);
                }
            }
        }

        if (!full) {
            #pragma unroll
            for (int nt = 0; nt < 8; nt++) {
                int kbase = kg0 + nt*8 + (lane & 3)*2;
                #pragma unroll
                for (int d = 0; d < 2; d++) {
                    int kidx = kbase + d;
                    bool ok0, ok1;
                    if (fwdh) { ok0 = (kidx <= qrow0); ok1 = (kidx <= qrow0 + 8); }
                    else      { int j = kidx - 1024; ok0 = (j >= qrow0); ok1 = (j >= qrow0 + 8); }
                    if (!ok0) s[nt][d]     = -1e30f;
                    if (!ok1) s[nt][d + 2] = -1e30f;
                }
            }
        }

        float mx0 = -1e30f, mx1 = -1e30f;
        #pragma unroll
        for (int nt = 0; nt < 8; nt++) {
            mx0 = fmaxf(mx0, fmaxf(s[nt][0], s[nt][1]));
            mx1 = fmaxf(mx1, fmaxf(s[nt][2], s[nt][3]));
        }
        mx0 = fmaxf(mx0, __shfl_xor_sync(0xffffffffu, mx0, 1));
        mx0 = fmaxf(mx0, __shfl_xor_sync(0xffffffffu, mx0, 2));
        mx1 = fmaxf(mx1, __shfl_xor_sync(0xffffffffu, mx1, 1));
        mx1 = fmaxf(mx1, __shfl_xor_sync(0xffffffffu, mx1, 2));
        float mn0 = fmaxf(m_i0, mx0), mn1 = fmaxf(m_i1, mx1);
        float sc0f = __expf(m_i0 - mn0), sc1f = __expf(m_i1 - mn1);
        m_i0 = mn0; m_i1 = mn1;
        float rs0 = 0.f, rs1 = 0.f;
        #pragma unroll
        for (int nt = 0; nt < 8; nt++) {
            s[nt][0] = __expf(s[nt][0] - mn0);
            s[nt][1] = __expf(s[nt][1] - mn0);
            s[nt][2] = __expf(s[nt][2] - mn1);
            s[nt][3] = __expf(s[nt][3] - mn1);
            rs0 += s[nt][0] + s[nt][1];
            rs1 += s[nt][2] + s[nt][3];
        }
        rs0 += __shfl_xor_sync(0xffffffffu, rs0, 1);
        rs0 += __shfl_xor_sync(0xffffffffu, rs0, 2);
        rs1 += __shfl_xor_sync(0xffffffffu, rs1, 1);
        rs1 += __shfl_xor_sync(0xffffffffu, rs1, 2);
        l_i0 = l_i0 * sc0f + rs0;
        l_i1 = l_i1 * sc1f + rs1;
        #pragma unroll
        for (int nt = 0; nt < 8; nt++) {
            om[nt][0] *= sc0f; om[nt][1] *= sc0f;
            om[nt][2] *= sc1f; om[nt][3] *= sc1f;
        }

        #pragma unroll
        for (int kc = 0; kc < 4; kc++) {
            uint32_t ph[4], pl[4];
            split2(s[2*kc][0],   s[2*kc][1],   ph[0], pl[0]);
            split2(s[2*kc][2],   s[2*kc][3],   ph[1], pl[1]);
            split2(s[2*kc+1][0], s[2*kc+1][1], ph[2], pl[2]);
            split2(s[2*kc+1][2], s[2*kc+1][3], ph[3], pl[3]);
            const int vm = lane >> 3, vr = lane & 7;
            #pragma unroll
            for (int hp0 = 0; hp0 < 4; hp0 += 2) {
                uint32_t vh4[2][4], vl4[2][4];
                #pragma unroll
                for (int p = 0; p < 2; p++) {
                    uint32_t vaddr = ((kc*16 + (vm & 1)*8 + vr)*FLS + (hp0+p)*16 + (vm >> 1)*8) * 2;
                    ldm_x4_t(vh4[p], kvb + 2*KVB*2 + vaddr);
                    ldm_x4_t(vl4[p], kvb + 3*KVB*2 + vaddr);
                }
                #pragma unroll
                for (int p = 0; p < 2; p++) {
                    mma16816(om[(hp0+p)*2],   ph, vh4[p][0], vh4[p][1]);
                    mma16816(om[(hp0+p)*2+1], ph, vh4[p][2], vh4[p][3]);
                }
                #pragma unroll
                for (int p = 0; p < 2; p++) {
                    mma16816(om[(hp0+p)*2],   pl, vh4[p][0], vh4[p][1]);
                    mma16816(om[(hp0+p)*2+1], pl, vh4[p][2], vh4[p][3]);
                }
                #pragma unroll
                for (int p = 0; p < 2; p++) {
                    mma16816(om[(hp0+p)*2],   ph, vl4[p][0], vl4[p][1]);
                    mma16816(om[(hp0+p)*2+1], ph, vl4[p][2], vl4[p][3]);
                }
            }
        }
        __syncthreads();   // fences stage reads before it gets re-staged (race-free)
    }

    float il0 = 1.f / l_i0, il1 = 1.f / l_i1;
    #pragma unroll
    for (int nt = 0; nt < 8; nt++) {
        int hd = nt*8 + (lane & 3)*2;
        uint32_t hi, lo;
        split2(om[nt][0]*il0, om[nt][1]*il0, hi, lo);
        *reinterpret_cast<uint32_t*>(oh + qoff + (size_t)qrow0*NC + hd) = hi;
        *reinterpret_cast<uint32_t*>(ol + qoff + (size_t)qrow0*NC + hd) = lo;
        split2(om[nt][2]*il1, om[nt][3]*il1, hi, lo);
        *reinterpret_cast<uint32_t*>(oh + qoff + (size_t)(qrow0+8)*NC + hd) = hi;
        *reinterpret_cast<uint32_t*>(ol + qoff + (size_t)(qrow0+8)*NC + hd) = lo;
    }
}

// ---------------------------------------------------------------------------
// Block reduction + LN kernels
// ---------------------------------------------------------------------------
__device__ __forceinline__ float2 block_reduce_sum2(float a, float b) {
    __shared__ float sha[8], shb[8];
    #pragma unroll
    for (int o = 16; o > 0; o >>= 1) {
        a += __shfl_xor_sync(0xffffffffu, a, o);
        b += __shfl_xor_sync(0xffffffffu, b, o);
    }
    int lane = threadIdx.x & 31, w = threadIdx.x >> 5;
    __syncthreads();
    if (lane == 0) { sha[w] = a; shb[w] = b; }
    __syncthreads();
    a = sha[lane & 7]; b = shb[lane & 7];
    #pragma unroll
    for (int o = 4; o > 0; o >>= 1) {
        a += __shfl_xor_sync(0xffffffffu, a, o);
        b += __shfl_xor_sync(0xffffffffu, b, o);
    }
    return make_float2(a, b);
}

__device__ __forceinline__ void store_split(__nv_bfloat16* hi, __nv_bfloat16* lo,
                                            size_t idx, float y) {
    __nv_bfloat16 hv = __float2bfloat16_rn(y);
    hi[idx] = hv;
    lo[idx] = __float2bfloat16_rn(y - __bfloat162float(hv));
}

__global__ void ln_all(const float* __restrict__ fwd, const float* __restrict__ bwd,
                       const float* __restrict__ g, const float* __restrict__ bta,
                       float* __restrict__ comb,
                       __nv_bfloat16* __restrict__ cxh, __nv_bfloat16* __restrict__ cxl,
                       __nv_bfloat16* __restrict__ aeh, __nv_bfloat16* __restrict__ ael)
{
    int z = blockIdx.x;
    if (z < NB*NS) {
        int row = z;
        int b = row / NS, s = row % NS;
        const float* fp = fwd + ((size_t)b*(NS+1) + s) * NC;
        const float* rp = bwd + ((size_t)b*(NS+1) + s + 1) * NC;
        const float rs2 = 0.70710678118654752f;
        float vals[4];
        float sum = 0.f, sq = 0.f;
        #pragma unroll
        for (int t = 0; t < 4; t++) {
            int i = threadIdx.x + t*256;
            float c = (fp[i] + rp[i]) * rs2;
            vals[t] = c; sum += c; sq += c*c;
            comb[(size_t)row*NC + i] = c;
        }
        float2 r2 = block_reduce_sum2(sum, sq);
        float mean = r2.x * (1.f/NC);
        float var  = r2.y * (1.f/NC) - mean*mean;
        float rinv = rsqrtf(var + 1e-5f);
        #pragma unroll
        for (int t = 0; t < 4; t++) {
            int i = threadIdx.x + t*256;
            store_split(cxh, cxl, (size_t)row*NC + i, (vals[t] - mean) * rinv * g[i] + bta[i]);
        }
    } else {
        int row = z - NB*NS;
        int b = row / (2*NS), t = row % (2*NS);
        const float* src = (t < NS) ? fwd + ((size_t)b*(NS+1) + t) * NC
                                    : bwd + ((size_t)b*(NS+1) + (t - NS) + 1) * NC;
        float vals[4];
        float sum = 0.f, sq = 0.f;
        #pragma unroll
        for (int u = 0; u < 4; u++) {
            int i = threadIdx.x + u*256;
            float c = src[i];
            vals[u] = c; sum += c; sq += c*c;
        }
        float2 r2 = block_reduce_sum2(sum, sq);
        float mean = r2.x * (1.f/NC);
        float var  = r2.y * (1.f/NC) - mean*mean;
        float rinv = rsqrtf(var + 1e-5f);
        #pragma unroll
        for (int u = 0; u < 4; u++) {
            int i = threadIdx.x + u*256;
            store_split(aeh, ael, (size_t)row*NC + i, (vals[u] - mean) * rinv * g[i] + bta[i]);
        }
    }
}

__global__ void double_ln_kernel(const float* __restrict__ xin,
                                 const float* __restrict__ g2, const float* __restrict__ b2,
                                 const float* __restrict__ gm, const float* __restrict__ bm,
                                 __nv_bfloat16* __restrict__ hh, __nv_bfloat16* __restrict__ hl)
{
    int row = blockIdx.x;
    const float* xp = xin + (size_t)row*NC;
    float vals[4];
    float s = 0.f, sq = 0.f;
    #pragma unroll
    for (int t = 0; t < 4; t++) {
        int i = threadIdx.x + t*256;
        float vv = xp[i];
        vals[t] = vv; s += vv; sq += vv*vv;
    }
    float2 r2 = block_reduce_sum2(s, sq);
    float mean = r2.x * (1.f/NC);
    float var  = r2.y * (1.f/NC) - mean*mean;
    float rinv = rsqrtf(var + 1e-5f);
    s = 0.f; sq = 0.f;
    #pragma unroll
    for (int t = 0; t < 4; t++) {
        int i = threadIdx.x + t*256;
        float y = (vals[t] - mean) * rinv * g2[i] + b2[i];
        vals[t] = y; s += y; sq += y*y;
    }
    r2 = block_reduce_sum2(s, sq);
    mean = r2.x * (1.f/NC);
    var  = r2.y * (1.f/NC) - mean*mean;
    rinv = rsqrtf(var + 1e-5f);
    #pragma unroll
    for (int t = 0; t < 4; t++) {
        int i = threadIdx.x + t*256;
        store_split(hh, hl, (size_t)row*NC + i, (vals[t] - mean) * rinv * gm[i] + bm[i]);
    }
}

// ---------------------------------------------------------------------------
// Launch
// ---------------------------------------------------------------------------
extern "C" void kernel_launch(void* const* d_in, const int* in_sizes, int n_in,
                              void* d_out, int out_size)
{
    (void)in_sizes; (void)n_in; (void)out_size;
    const float* fwd  = (const float*)d_in[0];
    const float* bwd  = (const float*)d_in[1];
    const float* pos  = (const float*)d_in[2];
    const float* ln1g = (const float*)d_in[3];
    const float* ln1b = (const float*)d_in[4];
    const float* Wq   = (const float*)d_in[5];
    const float* bq   = (const float*)d_in[6];
    const float* Wk   = (const float*)d_in[7];
    const float* bk   = (const float*)d_in[8];
    const float* Wv   = (const float*)d_in[9];
    const float* bv   = (const float*)d_in[10];
    const float* Wo   = (const float*)d_in[11];
    const float* bo   = (const float*)d_in[12];
    const float* ln2g = (const float*)d_in[13];
    const float* ln2b = (const float*)d_in[14];
    const float* mlpg = (const float*)d_in[15];
    const float* mlpb = (const float*)d_in[16];
    const float* W1   = (const float*)d_in[17];
    const float* b1   = (const float*)d_in[18];
    const float* W2   = (const float*)d_in[19];
    const float* b2   = (const float*)d_in[20];
    float* out = (float*)d_out;

    float *comb, *x;
    __nv_bfloat16 *cxh,*cxl,*aeh,*ael,*qh,*ql,*kh,*kl,*vh,*vl,*oh,*ol,*hh,*hl,*m1h,*m1l;
    __nv_bfloat16 *wthi, *wtlo;
    cudaGetSymbolAddress((void**)&comb, g_comb);
    cudaGetSymbolAddress((void**)&x,    g_x);
    cudaGetSymbolAddress((void**)&cxh,  g_cxh);  cudaGetSymbolAddress((void**)&cxl, g_cxl);
    cudaGetSymbolAddress((void**)&aeh,  g_aeh);  cudaGetSymbolAddress((void**)&ael, g_ael);
    cudaGetSymbolAddress((void**)&qh,   g_qh);   cudaGetSymbolAddress((void**)&ql,  g_ql);
    cudaGetSymbolAddress((void**)&kh,   g_kh);   cudaGetSymbolAddress((void**)&kl,  g_kl);
    cudaGetSymbolAddress((void**)&vh,   g_vh);   cudaGetSymbolAddress((void**)&vl,  g_vl);
    cudaGetSymbolAddress((void**)&oh,   g_oh);   cudaGetSymbolAddress((void**)&ol,  g_ol);
    cudaGetSymbolAddress((void**)&hh,   g_hh);   cudaGetSymbolAddress((void**)&hl,  g_hl);
    cudaGetSymbolAddress((void**)&m1h,  g_m1h);  cudaGetSymbolAddress((void**)&m1l, g_m1l);
    cudaGetSymbolAddress((void**)&wthi, g_wthi);
    cudaGetSymbolAddress((void**)&wtlo, g_wtlo);

    constexpr int SM128 = SMEM_OF<128>();
    constexpr int SM64  = SMEM_OF<64>();
    cudaFuncSetAttribute(mma_qkv,                      cudaFuncAttributeMaxDynamicSharedMemorySize, SM128);
    cudaFuncSetAttribute(mma_gemm<64,EPI_ADD,false>,   cudaFuncAttributeMaxDynamicSharedMemorySize, SM64);
    cudaFuncSetAttribute(mma_gemm<128,EPI_GELU,true>,  cudaFuncAttributeMaxDynamicSharedMemorySize, SM128);
    cudaFuncSetAttribute(flash_kernel,                 cudaFuncAttributeMaxDynamicSharedMemorySize, FLASH_SMEM);

    // 1: all weight transforms, one launch
    wt_split_all<<<12288, dim3(32, 8)>>>(Wq, Wk, Wv, Wo, W1, W2, wthi, wtlo);

    // 2: both LayerNorms, one launch
    ln_all<<<NB*NS + NB*2*NS, 256>>>(fwd, bwd, ln1g, ln1b, comb, cxh, cxl, aeh, ael);

    // 3: fused Q+K+V projections (640 CTAs, BM=128)
    mma_qkv<<<640, 256, SM128>>>(cxh, cxl, aeh, ael, wthi, wtlo,
                                 qh, ql, kh, kl, vh, vl, bq, bk, bv, pos);

    // 4: fused flash attention (73.7 KB smem -> 2 CTAs/SM solid)
    flash_kernel<<<dim3(NS/128, NB*NH), 256, FLASH_SMEM>>>(qh, ql, kh, kl, vh, vl, oh, ol);

    // 5: x = comb + (o @ Wo + bo)   [BM=64 -> 256 CTAs]
    mma_gemm<64,EPI_ADD,false><<<dim3(NC/128, (NB*NS)/64), 256, SM64>>>(
        oh, ol, NC, wthi + WT_O, wtlo + WT_O, x, nullptr, nullptr, NC, NC, bo, comb);

    // 6: h = LN(LN(x))
    double_ln_kernel<<<NB*NS, 256>>>(x, ln2g, ln2b, mlpg, mlpb, hh, hl);

    // 7: m1 = gelu(h @ W1 + b1)   [BM=128 -> 512 CTAs]
    mma_gemm<128,EPI_GELU,true><<<dim3((NE*NC)/128, (NB*NS)/128), 256, SM128>>>(
        hh, hl, NC, wthi + WT_1, wtlo + WT_1, nullptr, m1h, m1l, NE*NC, NC, b1, nullptr);

    // 8: out = x + (m1 @ W2 + b2)   [BM=64 -> 256 CTAs]
    mma_gemm<64,EPI_ADD,false><<<dim3(NC/128, (NB*NS)/64), 256, SM64>>>(
        m1h, m1l, NE*NC, wthi + WT_2, wtlo + WT_2, out, nullptr, nullptr, NC, NE*NC, b2, x);
}

// round 16
// speedup vs baseline: 1.0309x; 1.0204x over previous
#include <cuda_runtime.h>
#include <cuda_bf16.h>
#include <math.h>
#include <float.h>
#include <stdint.h>

// Problem constants
constexpr int NB = 2;
constexpr int NS = 1024;
constexpr int NC = 1024;
constexpr int NH = 16;
constexpr int HD = 64;
constexpr int NE = 4;

// ---------------------------------------------------------------------------
// Scratch (device globals)
// ---------------------------------------------------------------------------
__device__ float g_comb[NB*NS*NC];
__device__ float g_x   [NB*NS*NC];

__device__ __nv_bfloat16 g_cxh[NB*NS*NC],    g_cxl[NB*NS*NC];
__device__ __nv_bfloat16 g_aeh[NB*2*NS*NC],  g_ael[NB*2*NS*NC];
__device__ __nv_bfloat16 g_qh [NB*NS*NC],    g_ql [NB*NS*NC];
__device__ __nv_bfloat16 g_kh [NB*2*NS*NC],  g_kl [NB*2*NS*NC];
__device__ __nv_bfloat16 g_vh [NB*2*NS*NC],  g_vl [NB*2*NS*NC];
__device__ __nv_bfloat16 g_oh [NB*NS*NC],    g_ol [NB*NS*NC];
__device__ __nv_bfloat16 g_hh [NB*NS*NC],    g_hl [NB*NS*NC];
__device__ __nv_bfloat16 g_m1h[NB*NS*NE*NC], g_m1l[NB*NS*NE*NC];

__device__ __nv_bfloat16 g_wthi[12u<<20];
__device__ __nv_bfloat16 g_wtlo[12u<<20];
constexpr size_t WT_Q = 0;
constexpr size_t WT_K = (size_t)1<<20;
constexpr size_t WT_V = (size_t)2<<20;
constexpr size_t WT_O = (size_t)3<<20;
constexpr size_t WT_1 = (size_t)4<<20;
constexpr size_t WT_2 = (size_t)8<<20;

// ---------------------------------------------------------------------------
// Helpers
// ---------------------------------------------------------------------------
__device__ __forceinline__ uint32_t smem_u32(const void* p) {
    uint32_t a;
    asm("{ .reg .u64 t; cvta.to.shared.u64 t, %1; cvt.u32.u64 %0, t; }" : "=r"(a) : "l"(p));
    return a;
}
__device__ __forceinline__ uint32_t pack_bf(float a, float b) {
    __nv_bfloat162 h = __floats2bfloat162_rn(a, b);
    return *reinterpret_cast<uint32_t*>(&h);
}
__device__ __forceinline__ void split2(float a, float b, uint32_t& hi, uint32_t& lo) {
    __nv_bfloat16 ha = __float2bfloat16_rn(a);
    __nv_bfloat16 hb = __float2bfloat16_rn(b);
    hi = pack_bf(a, b);
    lo = pack_bf(a - __bfloat162float(ha), b - __bfloat162float(hb));
}
__device__ __forceinline__ void ldm_x4(uint32_t* r, uint32_t addr) {
    asm volatile("ldmatrix.sync.aligned.m8n8.x4.shared.b16 {%0,%1,%2,%3}, [%4];"
        : "=r"(r[0]), "=r"(r[1]), "=r"(r[2]), "=r"(r[3]) : "r"(addr));
}
__device__ __forceinline__ void ldm_x4_t(uint32_t* r, uint32_t addr) {
    asm volatile("ldmatrix.sync.aligned.m8n8.x4.trans.shared.b16 {%0,%1,%2,%3}, [%4];"
        : "=r"(r[0]), "=r"(r[1]), "=r"(r[2]), "=r"(r[3]) : "r"(addr));
}
__device__ __forceinline__ void mma16816(float* d, const uint32_t* a, uint32_t b0, uint32_t b1) {
    asm volatile(
        "mma.sync.aligned.m16n8k16.row.col.f32.bf16.bf16.f32 "
        "{%0,%1,%2,%3}, {%4,%5,%6,%7}, {%8,%9}, {%0,%1,%2,%3};"
        : "+f"(d[0]), "+f"(d[1]), "+f"(d[2]), "+f"(d[3])
        : "r"(a[0]), "r"(a[1]), "r"(a[2]), "r"(a[3]), "r"(b0), "r"(b1));
}
#define CP16(dst, src) \
    asm volatile("cp.async.cg.shared.global [%0], [%1], 16;" :: "r"(dst), "l"(src))
#define CP_COMMIT() asm volatile("cp.async.commit_group;")
#define CP_WAIT0()  asm volatile("cp.async.wait_group 0;")
#define CP_WAIT1()  asm volatile("cp.async.wait_group 1;")

// ---------------------------------------------------------------------------
// Merged weight transform
// ---------------------------------------------------------------------------
__global__ void wt_split_all(const float* __restrict__ Wq, const float* __restrict__ Wk,
                             const float* __restrict__ Wv, const float* __restrict__ Wo,
                             const float* __restrict__ W1, const float* __restrict__ W2,
                             __nv_bfloat16* __restrict__ hi_base,
                             __nv_bfloat16* __restrict__ lo_base)
{
    int z = blockIdx.x;
    const float* W; size_t off; int K, N, bx, by;
    if (z < 1024)      { W = Wq; off = WT_Q; K = 1024; N = 1024; bx = z & 31;  by = z >> 5; }
    else if (z < 2048) { int i = z - 1024; W = Wk; off = WT_K; K = 1024; N = 1024; bx = i & 31; by = i >> 5; }
    else if (z < 3072) { int i = z - 2048; W = Wv; off = WT_V; K = 1024; N = 1024; bx = i & 31; by = i >> 5; }
    else if (z < 4096) { int i = z - 3072; W = Wo; off = WT_O; K = 1024; N = 1024; bx = i & 31; by = i >> 5; }
    else if (z < 8192) { int i = z - 4096; W = W1; off = WT_1; K = 1024; N = 4096; bx = i & 127; by = i >> 7; }
    else               { int i = z - 8192; W = W2; off = WT_2; K = 4096; N = 1024; bx = i & 31;  by = i >> 5; }
    __nv_bfloat16* hi = hi_base + off;
    __nv_bfloat16* lo = lo_base + off;

    __shared__ float t[32][33];
    int n0 = bx * 32, k0 = by * 32;
    #pragma unroll
    for (int i = 0; i < 4; i++) {
        int k = k0 + threadIdx.y + 8*i;
        t[threadIdx.y + 8*i][threadIdx.x] = W[(size_t)k*N + n0 + threadIdx.x];
    }
    __syncthreads();
    #pragma unroll
    for (int i = 0; i < 4; i++) {
        int n = n0 + threadIdx.y + 8*i;
        int k = k0 + threadIdx.x;
        float v = t[threadIdx.x][threadIdx.y + 8*i];
        __nv_bfloat16 h = __float2bfloat16_rn(v);
        __nv_bfloat16 l = __float2bfloat16_rn(v - __bfloat162float(h));
        hi[(size_t)n*K + k] = h;
        lo[(size_t)n*K + k] = l;
    }
}

// ---------------------------------------------------------------------------
// GEMM core (round-12 structure: 2-stage, stage-before-wait, 2 barriers/chunk)
// ---------------------------------------------------------------------------
constexpr int BLDS = 40;

template<int BM> __host__ __device__ constexpr int NACC_OF() { return 2 * ((128 / (8 / (BM/32))) / 16); }
template<int BM> __host__ __device__ constexpr int SSZ_OF()  { return 2*BM*BLDS + 2*128*BLDS; }
template<int BM> __host__ __device__ constexpr int SMEM_OF() { return 2 * SSZ_OF<BM>() * 2; }

template<int BM, int NACC>
__device__ __forceinline__ void gemm_core(
    const __nv_bfloat16* __restrict__ Ahi, const __nv_bfloat16* __restrict__ Alo, int lda,
    const __nv_bfloat16* __restrict__ Bhi, const __nv_bfloat16* __restrict__ Blo, int K,
    int tileM, int tileN, uint32_t smb, float (&acc)[2][NACC][4])
{
    constexpr int WMW = BM/32;
    constexpr int WNW = 8/WMW;
    constexpr int NSPAN = 128/WNW;
    constexpr int NTP = NSPAN/16;
    static_assert(NACC == 2*NTP, "acc shape");
    static_assert((NTP & 1) == 0, "NTP even");
    constexpr int ASZ = BM*BLDS;
    constexpr int BSZ = 128*BLDS;
    constexpr int SSZ = 2*ASZ + 2*BSZ;

    const int tid = threadIdx.x, lane = tid & 31, wid = tid >> 5;
    const int wm = wid / WNW, wn = wid % WNW;
    const int a_row = wm*32 + (lane & 15);
    const int b_row = wn*NSPAN + (lane & 15);
    const int half8 = (lane >> 4) << 3;

    const int sr0 = tid >> 2, sc0 = (tid & 3) * 8;
    const int nch = K >> 5;

    // prologue: stage 0
    {
        #pragma unroll
        for (int p = 0; p < BM/64; p++) {
            int r = sr0 + p*64;
            uint32_t so = (r*BLDS + sc0) * 2;
            size_t ga = (size_t)(tileM + r)*lda + sc0;
            CP16(smb + so,           Ahi + ga);
            CP16(smb + ASZ*2 + so,   Alo + ga);
        }
        #pragma unroll
        for (int p = 0; p < 2; p++) {
            int r = sr0 + p*64;
            uint32_t so = (r*BLDS + sc0) * 2;
            size_t ga = (size_t)(tileN + r)*K + sc0;
            CP16(smb + 2*ASZ*2 + so,         Bhi + ga);
            CP16(smb + (2*ASZ+BSZ)*2 + so,   Blo + ga);
        }
        CP_COMMIT();
    }

    for (int c = 0; c < nch; c++) {
        const int st = c & 1;
        if (c + 1 < nch) {
            const int k0 = (c + 1) << 5;
            const uint32_t sb2 = smb + (uint32_t)((st ^ 1) * SSZ * 2);
            #pragma unroll
            for (int p = 0; p < BM/64; p++) {
                int r = sr0 + p*64;
                uint32_t so = (r*BLDS + sc0) * 2;
                size_t ga = (size_t)(tileM + r)*lda + k0 + sc0;
                CP16(sb2 + so,         Ahi + ga);
                CP16(sb2 + ASZ*2 + so, Alo + ga);
            }
            #pragma unroll
            for (int p = 0; p < 2; p++) {
                int r = sr0 + p*64;
                uint32_t so = (r*BLDS + sc0) * 2;
                size_t ga = (size_t)(tileN + r)*K + k0 + sc0;
                CP16(sb2 + 2*ASZ*2 + so,       Bhi + ga);
                CP16(sb2 + (2*ASZ+BSZ)*2 + so, Blo + ga);
            }
            CP_COMMIT();
            CP_WAIT1();
        } else {
            CP_WAIT0();
        }
        __syncthreads();

        const uint32_t sbase = smb + (uint32_t)(st * SSZ * 2);
        #pragma unroll
        for (int ks = 0; ks < 32; ks += 16) {
            uint32_t ahi[2][4], alo[2][4];
            #pragma unroll
            for (int mt = 0; mt < 2; mt++) {
                uint32_t off = ((a_row + mt*16)*BLDS + ks + half8) * 2;
                ldm_x4(ahi[mt], sbase + off);
                ldm_x4(alo[mt], sbase + ASZ*2 + off);
            }
            #pragma unroll
            for (int np0 = 0; np0 < NTP; np0 += 2) {
                uint32_t bh[2][4], bl[2][4];
                #pragma unroll
                for (int p = 0; p < 2; p++) {
                    uint32_t off = ((b_row + (np0+p)*16)*BLDS + ks + half8) * 2;
                    ldm_x4(bh[p], sbase + 2*ASZ*2 + off);
                    ldm_x4(bl[p], sbase + (2*ASZ+BSZ)*2 + off);
                }
                #pragma unroll
                for (int p = 0; p < 2; p++)
                    #pragma unroll
                    for (int mt = 0; mt < 2; mt++) {
                        mma16816(acc[mt][(np0+p)*2],   ahi[mt], bh[p][0], bh[p][2]);
                        mma16816(acc[mt][(np0+p)*2+1], ahi[mt], bh[p][1], bh[p][3]);
                    }
                #pragma unroll
                for (int p = 0; p < 2; p++)
                    #pragma unroll
                    for (int mt = 0; mt < 2; mt++) {
                        mma16816(acc[mt][(np0+p)*2],   ahi[mt], bl[p][0], bl[p][2]);
                        mma16816(acc[mt][(np0+p)*2+1], ahi[mt], bl[p][1], bl[p][3]);
                    }
                #pragma unroll
                for (int p = 0; p < 2; p++)
                    #pragma unroll
                    for (int mt = 0; mt < 2; mt++) {
                        mma16816(acc[mt][(np0+p)*2],   alo[mt], bh[p][0], bh[p][2]);
                        mma16816(acc[mt][(np0+p)*2+1], alo[mt], bh[p][1], bh[p][3]);
                    }
            }
        }
        __syncthreads();
    }
}

// ---------------------------------------------------------------------------
// Generic GEMM kernel (Wo / W1 / W2 paths)
// ---------------------------------------------------------------------------
enum { EPI_ADD = 3, EPI_GELU = 4 };

template<int BM, int EPI, bool SPLITOUT>
__global__ __launch_bounds__(256, 2)
void mma_gemm(const __nv_bfloat16* __restrict__ Ahi, const __nv_bfloat16* __restrict__ Alo,
              int lda,
              const __nv_bfloat16* __restrict__ Bhi, const __nv_bfloat16* __restrict__ Blo,
              float* __restrict__ C,
              __nv_bfloat16* __restrict__ Chi, __nv_bfloat16* __restrict__ Clo,
              int ldc, int K,
              const float* __restrict__ bias,
              const float* __restrict__ addm)
{
    extern __shared__ __nv_bfloat16 sm[];
    const uint32_t smb = smem_u32(sm);
    constexpr int NACC = NACC_OF<BM>();
    constexpr int WMW = BM/32;
    constexpr int WNW = 8/WMW;
    constexpr int NSPAN = 128/WNW;

    const int lane = threadIdx.x & 31, wid = threadIdx.x >> 5;
    const int wm = wid / WNW, wn = wid % WNW;
    const int tileM = blockIdx.y * BM;
    const int tileN = blockIdx.x * 128;

    float acc[2][NACC][4];
    #pragma unroll
    for (int i = 0; i < 2; i++)
        #pragma unroll
        for (int j = 0; j < NACC; j++)
            #pragma unroll
            for (int q = 0; q < 4; q++) acc[i][j][q] = 0.f;

    gemm_core<BM, NACC>(Ahi, Alo, lda, Bhi, Blo, K, tileM, tileN, smb, acc);

    #pragma unroll
    for (int mt = 0; mt < 2; mt++) {
        #pragma unroll
        for (int nt = 0; nt < NACC; nt++) {
            int gm = tileM + wm*32 + mt*16 + (lane >> 2);
            int gn = tileN + wn*NSPAN + nt*8 + (lane & 3)*2;
            #pragma unroll
            for (int half = 0; half < 2; half++) {
                int gmr = gm + half*8;
                float v0 = acc[mt][nt][half*2], v1 = acc[mt][nt][half*2+1];
                if (EPI == EPI_ADD) {
                    float2 am = *reinterpret_cast<const float2*>(addm + (size_t)gmr*ldc + gn);
                    v0 += bias[gn] + am.x; v1 += bias[gn+1] + am.y;
                } else if (EPI == EPI_GELU) {
                    float t0 = v0 + bias[gn], t1 = v1 + bias[gn+1];
                    v0 = 0.5f*t0*(1.f + erff(t0*0.70710678118654752f));
                    v1 = 0.5f*t1*(1.f + erff(t1*0.70710678118654752f));
                }
                if (SPLITOUT) {
                    uint32_t hi, lo;
                    split2(v0, v1, hi, lo);
                    *reinterpret_cast<uint32_t*>(Chi + (size_t)gmr*ldc + gn) = hi;
                    *reinterpret_cast<uint32_t*>(Clo + (size_t)gmr*ldc + gn) = lo;
                } else {
                    *reinterpret_cast<float2*>(C + (size_t)gmr*ldc + gn) = make_float2(v0, v1);
                }
            }
        }
    }
}

// ---------------------------------------------------------------------------
// Fused QKV GEMM: 640 CTAs (0..127 Q; 128..639 KV), BM=128
// ---------------------------------------------------------------------------
__global__ __launch_bounds__(256, 2)
void mma_qkv(const __nv_bfloat16* __restrict__ cxh, const __nv_bfloat16* __restrict__ cxl,
             const __nv_bfloat16* __restrict__ aeh, const __nv_bfloat16* __restrict__ ael,
             const __nv_bfloat16* __restrict__ wthi, const __nv_bfloat16* __restrict__ wtlo,
             __nv_bfloat16* __restrict__ qh, __nv_bfloat16* __restrict__ ql,
             __nv_bfloat16* __restrict__ kh, __nv_bfloat16* __restrict__ kl,
             __nv_bfloat16* __restrict__ vh, __nv_bfloat16* __restrict__ vl,
             const float* __restrict__ bq, const float* __restrict__ bk,
             const float* __restrict__ bv, const float* __restrict__ pos)
{
    extern __shared__ __nv_bfloat16 sm[];
    const uint32_t smb = smem_u32(sm);

    const int bz = blockIdx.x;
    const bool isQ = bz < 128;
    const __nv_bfloat16 *Ah, *Al, *Bh, *Bl;
    int tileM, tileN;
    if (isQ) {
        int nx = bz & 7, ny = bz >> 3;
        tileM = ny * 128; tileN = nx * 128;
        Ah = cxh; Al = cxl; Bh = wthi + WT_Q; Bl = wtlo + WT_Q;
    } else {
        int i = bz - 128;
        int nx = i & 15, ny = i >> 4;
        tileM = ny * 128; tileN = nx * 128;
        Ah = aeh; Al = ael; Bh = wthi + WT_K; Bl = wtlo + WT_K;
    }

    const int lane = threadIdx.x & 31, wid = threadIdx.x >> 5;
    const int wm = wid >> 1, wn = wid & 1;

    float acc[2][8][4];
    #pragma unroll
    for (int i = 0; i < 2; i++)
        #pragma unroll
        for (int j = 0; j < 8; j++)
            #pragma unroll
            for (int q = 0; q < 4; q++) acc[i][j][q] = 0.f;

    gemm_core<128, 8>(Ah, Al, NC, Bh, Bl, NC, tileM, tileN, smb, acc);

    #pragma unroll
    for (int mt = 0; mt < 2; mt++) {
        #pragma unroll
        for (int nt = 0; nt < 8; nt++) {
            int gm = tileM + wm*32 + mt*16 + (lane >> 2);
            int gn = tileN + wn*64 + nt*8 + (lane & 3)*2;
            #pragma unroll
            for (int half = 0; half < 2; half++) {
                int gmr = gm + half*8;
                float v0 = acc[mt][nt][half*2], v1 = acc[mt][nt][half*2+1];
                const float* pr = pos + (gmr % NS)*HD;
                uint32_t hi, lo;
                if (isQ) {
                    v0 = (v0 + bq[gn]   + pr[gn & (HD-1)])     * 0.125f;
                    v1 = (v1 + bq[gn+1] + pr[(gn+1) & (HD-1)]) * 0.125f;
                    split2(v0, v1, hi, lo);
                    *reinterpret_cast<uint32_t*>(qh + (size_t)gmr*NC + gn) = hi;
                    *reinterpret_cast<uint32_t*>(ql + (size_t)gmr*NC + gn) = lo;
                } else if (gn < NC) {
                    v0 = v0 + bk[gn]   + pr[gn & (HD-1)];
                    v1 = v1 + bk[gn+1] + pr[(gn+1) & (HD-1)];
                    split2(v0, v1, hi, lo);
                    *reinterpret_cast<uint32_t*>(kh + (size_t)gmr*NC + gn) = hi;
                    *reinterpret_cast<uint32_t*>(kl + (size_t)gmr*NC + gn) = lo;
                } else {
                    int gv = gn - NC;
                    v0 += bv[gv]; v1 += bv[gv+1];
                    split2(v0, v1, hi, lo);
                    *reinterpret_cast<uint32_t*>(vh + (size_t)gmr*NC + gv) = hi;
                    *reinterpret_cast<uint32_t*>(vl + (size_t)gmr*NC + gv) = lo;
                }
            }
        }
    }
}

// ---------------------------------------------------------------------------
// Flash attention v3 (round-15: Q region reused as KV stage A)
// ---------------------------------------------------------------------------
constexpr int FLS  = 72;
constexpr int FQ_HI = 0;
constexpr int FQ_LO = 128*FLS;
constexpr int KVB   = 64*FLS;
constexpr int KVST  = 4*KVB;
constexpr int STAGE_A = 0;
constexpr int STAGE_B = KVST;
constexpr int FLASH_SMEM = 2*KVST*2;      // 73728 bytes

__global__ __launch_bounds__(256, 2)
void flash_kernel(const __nv_bfloat16* __restrict__ qh, const __nv_bfloat16* __restrict__ ql,
                  const __nv_bfloat16* __restrict__ kh, const __nv_bfloat16* __restrict__ kl,
                  const __nv_bfloat16* __restrict__ vh, const __nv_bfloat16* __restrict__ vl,
                  __nv_bfloat16* __restrict__ oh, __nv_bfloat16* __restrict__ ol)
{
    extern __shared__ __nv_bfloat16 sf[];
    const uint32_t smb = smem_u32(sf);
    const int tid = threadIdx.x, lane = tid & 31, wid = tid >> 5;
    const int bh = blockIdx.y, b = bh >> 4, h = bh & 15;
    const int bx = blockIdx.x;
    const int q0 = bx * 128;
    const size_t qoff = (size_t)b*NS*NC   + h*HD;
    const size_t koff = (size_t)b*2*NS*NC + h*HD;

    const int sr = tid >> 2, sc0 = (tid & 3) * 16;

    {
        const int r = tid >> 1, c0 = (tid & 1) * 32;
        #pragma unroll
        for (int i = 0; i < 4; i++) {
            int cc = c0 + i*8;
            size_t ga = qoff + (size_t)(q0 + r)*NC + cc;
            uint32_t so = (r*FLS + cc) * 2;
            CP16(smb + FQ_HI*2 + so, qh + ga);
            CP16(smb + FQ_LO*2 + so, ql + ga);
        }
        uint32_t base = smb + (uint32_t)STAGE_B*2;
        #pragma unroll
        for (int i = 0; i < 2; i++) {
            int cc = sc0 + i*8;
            size_t ga = koff + (size_t)(0 + sr)*NC + cc;
            uint32_t so = (sr*FLS + cc) * 2;
            CP16(base + so,           kh + ga);
            CP16(base + KVB*2 + so,   kl + ga);
            CP16(base + 2*KVB*2 + so, vh + ga);
            CP16(base + 3*KVB*2 + so, vl + ga);
        }
        CP_COMMIT(); CP_WAIT0();
    }
    __syncthreads();

    const int arow = wid*16 + (lane & 15);
    const int half8 = (lane >> 4) << 3;
    uint32_t qhi4[4][4], qlo4[4][4];
    #pragma unroll
    for (int kc = 0; kc < 4; kc++) {
        uint32_t off = (arow*FLS + kc*16 + half8) * 2;
        ldm_x4(qhi4[kc], smb + FQ_HI*2 + off);
        ldm_x4(qlo4[kc], smb + FQ_LO*2 + off);
    }
    __syncthreads();

    float om[8][4];
    #pragma unroll
    for (int i = 0; i < 8; i++)
        #pragma unroll
        for (int j = 0; j < 4; j++) om[i][j] = 0.f;
    float m_i0 = -1e30f, m_i1 = -1e30f, l_i0 = 0.f, l_i1 = 0.f;

    const int qrow0 = q0 + wid*16 + (lane >> 2);

    const int fe = 2*bx + 1;
    const int bs = 16 + 2*bx;
    constexpr int NT_ACT = 18;

    for (int it = 0; it < NT_ACT; it++) {
        const int kt = (it <= fe) ? it : (bs + (it - fe - 1));
        const uint32_t cur_base  = (it & 1) ? (uint32_t)STAGE_A : (uint32_t)STAGE_B;
        const uint32_t next_base = (it & 1) ? (uint32_t)STAGE_B : (uint32_t)STAGE_A;

        if (it + 1 < NT_ACT) {
            const int ktn = (it + 1 <= fe) ? (it + 1) : (bs + (it + 1 - fe - 1));
            const int kg0n = ktn * 64;
            uint32_t base = smb + next_base*2;
            #pragma unroll
            for (int i = 0; i < 2; i++) {
                int cc = sc0 + i*8;
                size_t ga = koff + (size_t)(kg0n + sr)*NC + cc;
                uint32_t so = (sr*FLS + cc) * 2;
                CP16(base + so,           kh + ga);
                CP16(base + KVB*2 + so,   kl + ga);
                CP16(base + 2*KVB*2 + so, vh + ga);
                CP16(base + 3*KVB*2 + so, vl + ga);
            }
            CP_COMMIT();
            CP_WAIT1();
        } else {
            CP_WAIT0();
        }
        __syncthreads();

        const uint32_t kvb = smb + cur_base*2;
        const int kg0 = kt * 64;
        const bool fwdh = kt < 16;
        const bool full = fwdh ? (kt <= 2*bx - 1) : (kt >= 18 + 2*bx);

        float s[8][4];
        #pragma unroll
        for (int i = 0; i < 8; i++)
            #pragma unroll
            for (int j = 0; j < 4; j++) s[i][j] = 0.f;
        #pragma unroll
        for (int kc = 0; kc < 4; kc++) {
            #pragma unroll
            for (int np0 = 0; np0 < 4; np0 += 2) {
                uint32_t bh4[2][4], bl4[2][4];
                #pragma unroll
                for (int p = 0; p < 2; p++) {
                    uint32_t off = (((np0+p)*16 + (lane & 15))*FLS + kc*16 + half8) * 2;
                    ldm_x4(bh4[p], kvb + off);
                    ldm_x4(bl4[p], kvb + KVB*2 + off);
                }
                #pragma unroll
                for (int p = 0; p < 2; p++) {
                    mma16816(s[(np0+p)*2],   qhi4[kc], bh4[p][0], bh4[p][2]);
                    mma16816(s[(np0+p)*2+1], qhi4[kc], bh4[p][1], bh4[p][3]);
                }
                #pragma unroll
                for (int p = 0; p < 2; p++) {
                    mma16816(s[(np0+p)*2],   qhi4[kc], bl4[p][0], bl4[p][2]);
                    mma16816(s[(np0+p)*2+1], qhi4[kc], bl4[p][1], bl4[p][3]);
                }
                #pragma unroll
                for (int p = 0; p < 2; p++) {
                    mma16816(s[(np0+p)*2],   qlo4[kc], bh4[p][0], bh4[p][2]);
                    mma16816(s[(np0+p)*2+1], qlo4[kc], bh4[p][1], bh4[p][3]);
                }
            }
        }

        if (!full) {
            #pragma unroll
            for (int nt = 0; nt < 8; nt++) {
                int kbase = kg0 + nt*8 + (lane & 3)*2;
                #pragma unroll
                for (int d = 0; d < 2; d++) {
                    int kidx = kbase + d;
                    bool ok0, ok1;
                    if (fwdh) { ok0 = (kidx <= qrow0); ok1 = (kidx <= qrow0 + 8); }
                    else      { int j = kidx - 1024; ok0 = (j >= qrow0); ok1 = (j >= qrow0 + 8); }
                    if (!ok0) s[nt][d]     = -1e30f;
                    if (!ok1) s[nt][d + 2] = -1e30f;
                }
            }
        }

        float mx0 = -1e30f, mx1 = -1e30f;
        #pragma unroll
        for (int nt = 0; nt < 8; nt++) {
            mx0 = fmaxf(mx0, fmaxf(s[nt][0], s[nt][1]));
            mx1 = fmaxf(mx1, fmaxf(s[nt][2], s[nt][3]));
        }
        mx0 = fmaxf(mx0, __shfl_xor_sync(0xffffffffu, mx0, 1));
        mx0 = fmaxf(mx0, __shfl_xor_sync(0xffffffffu, mx0, 2));
        mx1 = fmaxf(mx1, __shfl_xor_sync(0xffffffffu, mx1, 1));
        mx1 = fmaxf(mx1, __shfl_xor_sync(0xffffffffu, mx1, 2));
        float mn0 = fmaxf(m_i0, mx0), mn1 = fmaxf(m_i1, mx1);
        float sc0f = __expf(m_i0 - mn0), sc1f = __expf(m_i1 - mn1);
        m_i0 = mn0; m_i1 = mn1;
        float rs0 = 0.f, rs1 = 0.f;
        #pragma unroll
        for (int nt = 0; nt < 8; nt++) {
            s[nt][0] = __expf(s[nt][0] - mn0);
            s[nt][1] = __expf(s[nt][1] - mn0);
            s[nt][2] = __expf(s[nt][2] - mn1);
            s[nt][3] = __expf(s[nt][3] - mn1);
            rs0 += s[nt][0] + s[nt][1];
            rs1 += s[nt][2] + s[nt][3];
        }
        rs0 += __shfl_xor_sync(0xffffffffu, rs0, 1);
        rs0 += __shfl_xor_sync(0xffffffffu, rs0, 2);
        rs1 += __shfl_xor_sync(0xffffffffu, rs1, 1);
        rs1 += __shfl_xor_sync(0xffffffffu, rs1, 2);
        l_i0 = l_i0 * sc0f + rs0;
        l_i1 = l_i1 * sc1f + rs1;
        #pragma unroll
        for (int nt = 0; nt < 8; nt++) {
            om[nt][0] *= sc0f; om[nt][1] *= sc0f;
            om[nt][2] *= sc1f; om[nt][3] *= sc1f;
        }

        #pragma unroll
        for (int kc = 0; kc < 4; kc++) {
            uint32_t ph[4], pl[4];
            split2(s[2*kc][0],   s[2*kc][1],   ph[0], pl[0]);
            split2(s[2*kc][2],   s[2*kc][3],   ph[1], pl[1]);
            split2(s[2*kc+1][0], s[2*kc+1][1], ph[2], pl[2]);
            split2(s[2*kc+1][2], s[2*kc+1][3], ph[3], pl[3]);
            const int vm = lane >> 3, vr = lane & 7;
            #pragma unroll
            for (int hp0 = 0; hp0 < 4; hp0 += 2) {
                uint32_t vh4[2][4], vl4[2][4];
                #pragma unroll
                for (int p = 0; p < 2; p++) {
                    uint32_t vaddr = ((kc*16 + (vm & 1)*8 + vr)*FLS + (hp0+p)*16 + (vm >> 1)*8) * 2;
                    ldm_x4_t(vh4[p], kvb + 2*KVB*2 + vaddr);
                    ldm_x4_t(vl4[p], kvb + 3*KVB*2 + vaddr);
                }
                #pragma unroll
                for (int p = 0; p < 2; p++) {
                    mma16816(om[(hp0+p)*2],   ph, vh4[p][0], vh4[p][1]);
                    mma16816(om[(hp0+p)*2+1], ph, vh4[p][2], vh4[p][3]);
                }
                #pragma unroll
                for (int p = 0; p < 2; p++) {
                    mma16816(om[(hp0+p)*2],   pl, vh4[p][0], vh4[p][1]);
                    mma16816(om[(hp0+p)*2+1], pl, vh4[p][2], vh4[p][3]);
                }
                #pragma unroll
                for (int p = 0; p < 2; p++) {
                    mma16816(om[(hp0+p)*2],   ph, vl4[p][0], vl4[p][1]);
                    mma16816(om[(hp0+p)*2+1], ph, vl4[p][2], vl4[p][3]);
                }
            }
        }
        __syncthreads();
    }

    float il0 = 1.f / l_i0, il1 = 1.f / l_i1;
    #pragma unroll
    for (int nt = 0; nt < 8; nt++) {
        int hd = nt*8 + (lane & 3)*2;
        uint32_t hi, lo;
        split2(om[nt][0]*il0, om[nt][1]*il0, hi, lo);
        *reinterpret_cast<uint32_t*>(oh + qoff + (size_t)qrow0*NC + hd) = hi;
        *reinterpret_cast<uint32_t*>(ol + qoff + (size_t)qrow0*NC + hd) = lo;
        split2(om[nt][2]*il1, om[nt][3]*il1, hi, lo);
        *reinterpret_cast<uint32_t*>(oh + qoff + (size_t)(qrow0+8)*NC + hd) = hi;
        *reinterpret_cast<uint32_t*>(ol + qoff + (size_t)(qrow0+8)*NC + hd) = lo;
    }
}

// ---------------------------------------------------------------------------
// Block reduction + LN kernels
// ---------------------------------------------------------------------------
__device__ __forceinline__ float2 block_reduce_sum2(float a, float b) {
    __shared__ float sha[8], shb[8];
    #pragma unroll
    for (int o = 16; o > 0; o >>= 1) {
        a += __shfl_xor_sync(0xffffffffu, a, o);
        b += __shfl_xor_sync(0xffffffffu, b, o);
    }
    int lane = threadIdx.x & 31, w = threadIdx.x >> 5;
    __syncthreads();
    if (lane == 0) { sha[w] = a; shb[w] = b; }
    __syncthreads();
    a = sha[lane & 7]; b = shb[lane & 7];
    #pragma unroll
    for (int o = 4; o > 0; o >>= 1) {
        a += __shfl_xor_sync(0xffffffffu, a, o);
        b += __shfl_xor_sync(0xffffffffu, b, o);
    }
    return make_float2(a, b);
}

__device__ __forceinline__ void store_split(__nv_bfloat16* hi, __nv_bfloat16* lo,
                                            size_t idx, float y) {
    __nv_bfloat16 hv = __float2bfloat16_rn(y);
    hi[idx] = hv;
    lo[idx] = __float2bfloat16_rn(y - __bfloat162float(hv));
}

__global__ void ln_all(const float* __restrict__ fwd, const float* __restrict__ bwd,
                       const float* __restrict__ g, const float* __restrict__ bta,
                       float* __restrict__ comb,
                       __nv_bfloat16* __restrict__ cxh, __nv_bfloat16* __restrict__ cxl,
                       __nv_bfloat16* __restrict__ aeh, __nv_bfloat16* __restrict__ ael)
{
    int z = blockIdx.x;
    if (z < NB*NS) {
        int row = z;
        int b = row / NS, s = row % NS;
        const float* fp = fwd + ((size_t)b*(NS+1) + s) * NC;
        const float* rp = bwd + ((size_t)b*(NS+1) + s + 1) * NC;
        const float rs2 = 0.70710678118654752f;
        float vals[4];
        float sum = 0.f, sq = 0.f;
        #pragma unroll
        for (int t = 0; t < 4; t++) {
            int i = threadIdx.x + t*256;
            float c = (fp[i] + rp[i]) * rs2;
            vals[t] = c; sum += c; sq += c*c;
            comb[(size_t)row*NC + i] = c;
        }
        float2 r2 = block_reduce_sum2(sum, sq);
        float mean = r2.x * (1.f/NC);
        float var  = r2.y * (1.f/NC) - mean*mean;
        float rinv = rsqrtf(var + 1e-5f);
        #pragma unroll
        for (int t = 0; t < 4; t++) {
            int i = threadIdx.x + t*256;
            store_split(cxh, cxl, (size_t)row*NC + i, (vals[t] - mean) * rinv * g[i] + bta[i]);
        }
    } else {
        int row = z - NB*NS;
        int b = row / (2*NS), t = row % (2*NS);
        const float* src = (t < NS) ? fwd + ((size_t)b*(NS+1) + t) * NC
                                    : bwd + ((size_t)b*(NS+1) + (t - NS) + 1) * NC;
        float vals[4];
        float sum = 0.f, sq = 0.f;
        #pragma unroll
        for (int u = 0; u < 4; u++) {
            int i = threadIdx.x + u*256;
            float c = src[i];
            vals[u] = c; sum += c; sq += c*c;
        }
        float2 r2 = block_reduce_sum2(sum, sq);
        float mean = r2.x * (1.f/NC);
        float var  = r2.y * (1.f/NC) - mean*mean;
        float rinv = rsqrtf(var + 1e-5f);
        #pragma unroll
        for (int u = 0; u < 4; u++) {
            int i = threadIdx.x + u*256;
            store_split(aeh, ael, (size_t)row*NC + i, (vals[u] - mean) * rinv * g[i] + bta[i]);
        }
    }
}

__global__ void double_ln_kernel(const float* __restrict__ xin,
                                 const float* __restrict__ g2, const float* __restrict__ b2,
                                 const float* __restrict__ gm, const float* __restrict__ bm,
                                 __nv_bfloat16* __restrict__ hh, __nv_bfloat16* __restrict__ hl)
{
    int row = blockIdx.x;
    const float* xp = xin + (size_t)row*NC;
    float vals[4];
    float s = 0.f, sq = 0.f;
    #pragma unroll
    for (int t = 0; t < 4; t++) {
        int i = threadIdx.x + t*256;
        float vv = xp[i];
        vals[t] = vv; s += vv; sq += vv*vv;
    }
    float2 r2 = block_reduce_sum2(s, sq);
    float mean = r2.x * (1.f/NC);
    float var  = r2.y * (1.f/NC) - mean*mean;
    float rinv = rsqrtf(var + 1e-5f);
    s = 0.f; sq = 0.f;
    #pragma unroll
    for (int t = 0; t < 4; t++) {
        int i = threadIdx.x + t*256;
        float y = (vals[t] - mean) * rinv * g2[i] + b2[i];
        vals[t] = y; s += y; sq += y*y;
    }
    r2 = block_reduce_sum2(s, sq);
    mean = r2.x * (1.f/NC);
    var  = r2.y * (1.f/NC) - mean*mean;
    rinv = rsqrtf(var + 1e-5f);
    #pragma unroll
    for (int t = 0; t < 4; t++) {
        int i = threadIdx.x + t*256;
        store_split(hh, hl, (size_t)row*NC + i, (vals[t] - mean) * rinv * gm[i] + bm[i]);
    }
}

// ---------------------------------------------------------------------------
// Launch
// ---------------------------------------------------------------------------
extern "C" void kernel_launch(void* const* d_in, const int* in_sizes, int n_in,
                              void* d_out, int out_size)
{
    (void)in_sizes; (void)n_in; (void)out_size;
    const float* fwd  = (const float*)d_in[0];
    const float* bwd  = (const float*)d_in[1];
    const float* pos  = (const float*)d_in[2];
    const float* ln1g = (const float*)d_in[3];
    const float* ln1b = (const float*)d_in[4];
    const float* Wq   = (const float*)d_in[5];
    const float* bq   = (const float*)d_in[6];
    const float* Wk   = (const float*)d_in[7];
    const float* bk   = (const float*)d_in[8];
    const float* Wv   = (const float*)d_in[9];
    const float* bv   = (const float*)d_in[10];
    const float* Wo   = (const float*)d_in[11];
    const float* bo   = (const float*)d_in[12];
    const float* ln2g = (const float*)d_in[13];
    const float* ln2b = (const float*)d_in[14];
    const float* mlpg = (const float*)d_in[15];
    const float* mlpb = (const float*)d_in[16];
    const float* W1   = (const float*)d_in[17];
    const float* b1   = (const float*)d_in[18];
    const float* W2   = (const float*)d_in[19];
    const float* b2   = (const float*)d_in[20];
    float* out = (float*)d_out;

    float *comb, *x;
    __nv_bfloat16 *cxh,*cxl,*aeh,*ael,*qh,*ql,*kh,*kl,*vh,*vl,*oh,*ol,*hh,*hl,*m1h,*m1l;
    __nv_bfloat16 *wthi, *wtlo;
    cudaGetSymbolAddress((void**)&comb, g_comb);
    cudaGetSymbolAddress((void**)&x,    g_x);
    cudaGetSymbolAddress((void**)&cxh,  g_cxh);  cudaGetSymbolAddress((void**)&cxl, g_cxl);
    cudaGetSymbolAddress((void**)&aeh,  g_aeh);  cudaGetSymbolAddress((void**)&ael, g_ael);
    cudaGetSymbolAddress((void**)&qh,   g_qh);   cudaGetSymbolAddress((void**)&ql,  g_ql);
    cudaGetSymbolAddress((void**)&kh,   g_kh);   cudaGetSymbolAddress((void**)&kl,  g_kl);
    cudaGetSymbolAddress((void**)&vh,   g_vh);   cudaGetSymbolAddress((void**)&vl,  g_vl);
    cudaGetSymbolAddress((void**)&oh,   g_oh);   cudaGetSymbolAddress((void**)&ol,  g_ol);
    cudaGetSymbolAddress((void**)&hh,   g_hh);   cudaGetSymbolAddress((void**)&hl,  g_hl);
    cudaGetSymbolAddress((void**)&m1h,  g_m1h);  cudaGetSymbolAddress((void**)&m1l, g_m1l);
    cudaGetSymbolAddress((void**)&wthi, g_wthi);
    cudaGetSymbolAddress((void**)&wtlo, g_wtlo);

    constexpr int SM128 = SMEM_OF<128>();
    cudaFuncSetAttribute(mma_qkv,                      cudaFuncAttributeMaxDynamicSharedMemorySize, SM128);
    cudaFuncSetAttribute(mma_gemm<128,EPI_ADD,false>,  cudaFuncAttributeMaxDynamicSharedMemorySize, SM128);
    cudaFuncSetAttribute(mma_gemm<128,EPI_GELU,true>,  cudaFuncAttributeMaxDynamicSharedMemorySize, SM128);
    cudaFuncSetAttribute(flash_kernel,                 cudaFuncAttributeMaxDynamicSharedMemorySize, FLASH_SMEM);

    // 1: all weight transforms, one launch
    wt_split_all<<<12288, dim3(32, 8)>>>(Wq, Wk, Wv, Wo, W1, W2, wthi, wtlo);

    // 2: both LayerNorms, one launch
    ln_all<<<NB*NS + NB*2*NS, 256>>>(fwd, bwd, ln1g, ln1b, comb, cxh, cxl, aeh, ael);

    // 3: fused Q+K+V projections (640 CTAs, BM=128)
    mma_qkv<<<640, 256, SM128>>>(cxh, cxl, aeh, ael, wthi, wtlo,
                                 qh, ql, kh, kl, vh, vl, bq, bk, bv, pos);

    // 4: fused flash attention
    flash_kernel<<<dim3(NS/128, NB*NH), 256, FLASH_SMEM>>>(qh, ql, kh, kl, vh, vl, oh, ol);

    // 5: x = comb + (o @ Wo + bo)   [BM=128 -> 128 CTAs, LDGSTS-optimal tile]
    mma_gemm<128,EPI_ADD,false><<<dim3(NC/128, (NB*NS)/128), 256, SM128>>>(
        oh, ol, NC, wthi + WT_O, wtlo + WT_O, x, nullptr, nullptr, NC, NC, bo, comb);

    // 6: h = LN(LN(x))
    double_ln_kernel<<<NB*NS, 256>>>(x, ln2g, ln2b, mlpg, mlpb, hh, hl);

    // 7: m1 = gelu(h @ W1 + b1)   [BM=128 -> 512 CTAs]
    mma_gemm<128,EPI_GELU,true><<<dim3((NE*NC)/128, (NB*NS)/128), 256, SM128>>>(
        hh, hl, NC, wthi + WT_1, wtlo + WT_1, nullptr, m1h, m1l, NE*NC, NC, b1, nullptr);

    // 8: out = x + (m1 @ W2 + b2)   [BM=128 -> 128 CTAs, K=4096 traffic halved vs BM=64]
    mma_gemm<128,EPI_ADD,false><<<dim3(NC/128, (NB*NS)/128), 256, SM128>>>(
        m1h, m1l, NE*NC, wthi + WT_2, wtlo + WT_2, out, nullptr, nullptr, NC, NE*NC, b2, x);
}